// round 1
// baseline (speedup 1.0000x reference)
#include <cuda_runtime.h>
#include <cuda_bf16.h>

// Problem constants
#define AN   32      // agents
#define OBS  128
#define EDIM 64
#define DDIM 64
#define HHEADS 4
#define RDIM 256
#define NACT 16
#define ZDIM 192     // OBS + EDIM
#define MAXROWS (4096*32)

// Scratch: XR = relu(fc1([inputs, att]))  [B*A, 256]
__device__ float g_xr[MAXROWS * RDIM];

__device__ __forceinline__ float sigf(float x) { return 1.0f / (1.0f + __expf(-x)); }

// ---------------------------------------------------------------------------
// Kernel 1: per-batch GAT + fc1  (one CTA per batch element b, 256 threads)
// ---------------------------------------------------------------------------
// smem layout (bytes):
//  [0      ,16384)  X[32][128]
//  [16384  ,24576)  xe[32][64]
//  [24576  ,57856)  bufA: WfcT[128][65]  then  hsm[4][32][64]
//  [57856  ,58368)  ssrc[128]
//  [58368  ,58880)  sdst[128]
//  [58880  ,62976)  msk[32][32] (int)
//  [62976  ,79360)  alpha[4][32][32]  then  att[32][64]
//  [79360  ,112256) bufB: agg[32][256]  then  f1T[32][257]
#define SMEM1 112256

__global__ void __launch_bounds__(256) k1_gat_fc1(
    const float* __restrict__ inputs, const int* __restrict__ mask,
    const float* __restrict__ Wfc, const float* __restrict__ bfc,
    const float* __restrict__ Wh,  const float* __restrict__ asrc,
    const float* __restrict__ adst,const float* __restrict__ Wo,
    const float* __restrict__ bo,  const float* __restrict__ W1,
    const float* __restrict__ b1,  float* __restrict__ xr_out)
{
    extern __shared__ char sm[];
    float* X    = (float*)(sm);
    float* xe   = (float*)(sm + 16384);
    float* bufA = (float*)(sm + 24576);
    float* ssrc = (float*)(sm + 57856);
    float* sdst = (float*)(sm + 58368);
    int*   msk  = (int*)  (sm + 58880);
    float* alpha= (float*)(sm + 62976);
    float* att  = alpha;                  // overlays alpha after it is dead
    float* bufB = (float*)(sm + 79360);

    const int tid = threadIdx.x;
    const int b   = blockIdx.x;

    // ---- load inputs, mask, transposed gat_fc weight ----
    const float* inb = inputs + (size_t)b * (AN * OBS);
    for (int i = tid; i < AN * OBS; i += 256) X[i] = inb[i];
    for (int i = tid; i < AN * AN;  i += 256) msk[i] = mask[(size_t)b * AN * AN + i];
    for (int i = tid; i < EDIM * OBS; i += 256) {
        int e = i >> 7, o = i & 127;
        bufA[o * 65 + e] = Wfc[i];        // WfcT[o][e], pitch 65 (conflict-free)
    }
    __syncthreads();

    // ---- S1: xe = X @ Wfc^T + bfc   [32,64] ----
    for (int out = tid; out < AN * EDIM; out += 256) {
        int a = out >> 6, e = out & 63;
        float acc = bfc[e];
        const float* xrow = X + a * OBS;
        #pragma unroll 8
        for (int o = 0; o < OBS; ++o) acc = fmaf(xrow[o], bufA[o * 65 + e], acc);
        xe[out] = acc;
    }
    __syncthreads();

    // ---- S2: h[hd][a][d] = xe @ W_h   (overwrites bufA) ----
    float* hsm = bufA;
    for (int out = tid; out < HHEADS * AN * DDIM; out += 256) {
        int d = out & 63, a = (out >> 6) & 31, hd = out >> 11;
        float acc = 0.f;
        const float* xr_ = xe + a * 64;
        const float* wp  = Wh + (size_t)hd * EDIM * DDIM + d;
        #pragma unroll 8
        for (int e = 0; e < EDIM; ++e) acc = fmaf(xr_[e], wp[e * 64], acc);
        hsm[(hd * 32 + a) * 64 + d] = acc;
    }
    __syncthreads();

    // ---- s_src / s_dst: one warp per group of rows ----
    {
        int warp = tid >> 5, lane = tid & 31;
        for (int row = warp; row < HHEADS * AN; row += 8) {
            int hd = row >> 5;
            const float* hr = hsm + row * 64;
            float vs = hr[lane] * asrc[hd * 64 + lane] + hr[lane + 32] * asrc[hd * 64 + lane + 32];
            float vd = hr[lane] * adst[hd * 64 + lane] + hr[lane + 32] * adst[hd * 64 + lane + 32];
            #pragma unroll
            for (int o = 16; o; o >>= 1) {
                vs += __shfl_xor_sync(0xffffffffu, vs, o);
                vd += __shfl_xor_sync(0xffffffffu, vd, o);
            }
            if (lane == 0) { ssrc[row] = vs; sdst[row] = vd; }
        }
    }
    __syncthreads();

    // ---- S3: masked-softmax attention weights alpha[hd][i][j] ----
    if (tid < HHEADS * AN) {
        int hd = tid >> 5, i = tid & 31;
        float si = ssrc[tid];
        float v[32];
        float m = -3.4e38f;
        #pragma unroll
        for (int j = 0; j < 32; ++j) {
            float e_ = si + sdst[hd * 32 + j];
            float l  = e_ > 0.f ? e_ : 0.2f * e_;           // leaky_relu(0.2)
            if (msk[i * 32 + j] <= 0) l = -1e9f;
            v[j] = l; m = fmaxf(m, l);
        }
        float s = 0.f;
        #pragma unroll
        for (int j = 0; j < 32; ++j) { v[j] = __expf(v[j] - m); s += v[j]; }
        float inv = 1.f / s;
        #pragma unroll
        for (int j = 0; j < 32; ++j) alpha[tid * 32 + j] = v[j] * inv;
    }
    __syncthreads();

    // ---- S4: agg[a][hd*64+d] = alpha @ h  (into bufB) ----
    float* agg = bufB;
    for (int out = tid; out < AN * HHEADS * DDIM; out += 256) {
        int d = out & 63, hd = (out >> 6) & 3, a = out >> 8;
        const float* al = alpha + (hd * 32 + a) * 32;
        const float* hj = hsm + (hd * 32) * 64 + d;
        float acc = 0.f;
        #pragma unroll
        for (int j = 0; j < 32; ++j) acc = fmaf(al[j], hj[j * 64], acc);
        agg[a * 256 + hd * 64 + d] = acc;
    }
    __syncthreads();

    // ---- S5: att = agg @ W_o + b_o  (overlays alpha) ----
    for (int out = tid; out < AN * EDIM; out += 256) {
        int a = out >> 6, e = out & 63;
        float acc = bo[e];
        const float* ag = agg + a * 256;
        const float* wp = Wo + e;
        #pragma unroll 8
        for (int k = 0; k < 256; ++k) acc = fmaf(ag[k], wp[k * 64], acc);
        att[a * 64 + e] = acc;
    }
    __syncthreads();

    // ---- S6: xr = relu([X, att] @ fc1_w^T + fc1_b) ----
    // thread tid owns output column r = tid for all 32 rows (a).
    float* f1T = bufB;   // [32][257]  (overlays agg)
    float acc[32];
    {
        float bb = b1[tid];
        #pragma unroll
        for (int a = 0; a < 32; ++a) acc[a] = bb;
    }
    for (int kt = 0; kt < 6; ++kt) {
        __syncthreads();
        for (int idx = tid; idx < 256 * 32; idx += 256) {
            int kk = idx & 31, r = idx >> 5;
            f1T[kk * 257 + r] = W1[r * ZDIM + kt * 32 + kk];
        }
        __syncthreads();
        const float* zb; int pitch;
        if (kt < 4) { zb = X + kt * 32;        pitch = OBS; }
        else        { zb = att + (kt - 4) * 32; pitch = 64; }
        #pragma unroll
        for (int kkg = 0; kkg < 8; ++kkg) {
            float w0 = f1T[(kkg * 4 + 0) * 257 + tid];
            float w1 = f1T[(kkg * 4 + 1) * 257 + tid];
            float w2 = f1T[(kkg * 4 + 2) * 257 + tid];
            float w3 = f1T[(kkg * 4 + 3) * 257 + tid];
            #pragma unroll
            for (int a = 0; a < 32; ++a) {
                const float4 u = *(const float4*)(zb + a * pitch + kkg * 4);
                acc[a] = fmaf(u.x, w0, fmaf(u.y, w1, fmaf(u.z, w2, fmaf(u.w, w3, acc[a]))));
            }
        }
    }
    {
        size_t rowbase = (size_t)b * 32;
        #pragma unroll
        for (int a = 0; a < 32; ++a)
            xr_out[(rowbase + a) * RDIM + tid] = fmaxf(acc[a], 0.f);
    }
}

// ---------------------------------------------------------------------------
// Kernel 2: fused GRU GEMM + gates -> hh
// grid = (B*A/32, 4);  CTA tile = 32 rows x 64 gate-columns, 256 threads
// ---------------------------------------------------------------------------
// smem: UT[512][36] transposed [xr | h] (73728 B) + Wt[3][32][65] (24960 B)
#define SMEM2 (73728 + 24960)

__global__ void __launch_bounds__(256, 2) k2_gru(
    const float* __restrict__ xr,  const float* __restrict__ hin,
    const float* __restrict__ Wih, const float* __restrict__ Whh,
    const float* __restrict__ bih, const float* __restrict__ bhh,
    float* __restrict__ hh_out)
{
    extern __shared__ float smf[];
    float* UT = smf;                 // [512][36]
    float* Wt = smf + 512 * 36;      // [3][32][65]

    const int tid = threadIdx.x;
    const int tx  = tid & 63;        // gate column within span
    const int ty  = tid >> 6;        // row group (8 rows each)
    const size_t r0 = (size_t)blockIdx.x * 32;
    const int c0 = blockIdx.y * 64;

    // load transposed activations: UT[k][rr]; k<256 = xr, k>=256 = h_in
    for (int idx = tid; idx < 32 * 256; idx += 256) {
        int k = idx & 255, rr = idx >> 8;
        UT[k * 36 + rr]          = xr [(r0 + rr) * RDIM + k];
        UT[(256 + k) * 36 + rr]  = hin[(r0 + rr) * RDIM + k];
    }

    float acc[2][8][3];
    #pragma unroll
    for (int p = 0; p < 2; ++p)
        #pragma unroll
        for (int j = 0; j < 8; ++j)
            #pragma unroll
            for (int g = 0; g < 3; ++g) acc[p][j][g] = 0.f;

    #pragma unroll
    for (int ph = 0; ph < 2; ++ph) {
        const float* W = (ph == 0) ? Wih : Whh;
        for (int kt = 0; kt < 8; ++kt) {
            __syncthreads();
            // stage weight tile: rows {c, 256+c, 512+c} for c in [c0,c0+64), k-tile of 32
            for (int idx = tid; idx < 6144; idx += 256) {
                int kk = idx & 31, cl = (idx >> 5) & 63, g = idx >> 11;
                Wt[g * 2080 + kk * 65 + cl] = W[(size_t)(g * 256 + c0 + cl) * 256 + (kt << 5) + kk];
            }
            __syncthreads();
            int kb = ph * 256 + kt * 32;
            #pragma unroll
            for (int kk = 0; kk < 32; ++kk) {
                const float* up = &UT[(kb + kk) * 36 + ty * 8];
                float4 ua = *(const float4*)up;
                float4 ub = *(const float4*)(up + 4);
                float u[8] = {ua.x, ua.y, ua.z, ua.w, ub.x, ub.y, ub.z, ub.w};
                float w0 = Wt[           kk * 65 + tx];
                float w1 = Wt[1 * 2080 + kk * 65 + tx];
                float w2 = Wt[2 * 2080 + kk * 65 + tx];
                #pragma unroll
                for (int j = 0; j < 8; ++j) {
                    acc[ph][j][0] = fmaf(u[j], w0, acc[ph][j][0]);
                    acc[ph][j][1] = fmaf(u[j], w1, acc[ph][j][1]);
                    acc[ph][j][2] = fmaf(u[j], w2, acc[ph][j][2]);
                }
            }
        }
    }

    // gates + output (UT still holds h_in for hprev)
    const int c = c0 + tx;
    const float bi_r = bih[c], bi_z = bih[256 + c], bi_n = bih[512 + c];
    const float bh_r = bhh[c], bh_z = bhh[256 + c], bh_n = bhh[512 + c];
    #pragma unroll
    for (int j = 0; j < 8; ++j) {
        size_t row = r0 + ty * 8 + j;
        float hprev = UT[(256 + c) * 36 + ty * 8 + j];
        float rg = sigf(acc[0][j][0] + bi_r + acc[1][j][0] + bh_r);
        float zg = sigf(acc[0][j][1] + bi_z + acc[1][j][1] + bh_z);
        float ng = tanhf(acc[0][j][2] + bi_n + rg * (acc[1][j][2] + bh_n));
        hh_out[row * RDIM + c] = (1.f - zg) * ng + zg * hprev;
    }
}

// ---------------------------------------------------------------------------
// Kernel 3: LayerNorm + fc2 (one warp per row)
// ---------------------------------------------------------------------------
__global__ void __launch_bounds__(256) k3_ln_fc2(
    const float* __restrict__ hh, const float* __restrict__ lng,
    const float* __restrict__ lnb, const float* __restrict__ W2,
    const float* __restrict__ b2, float* __restrict__ q, int nrows)
{
    int warp = (blockIdx.x * blockDim.x + threadIdx.x) >> 5;
    int lane = threadIdx.x & 31;
    if (warp >= nrows) return;
    const float* hr = hh + (size_t)warp * RDIM;

    float v[8];
    float s = 0.f;
    #pragma unroll
    for (int i = 0; i < 8; ++i) { v[i] = hr[lane + 32 * i]; s += v[i]; }
    #pragma unroll
    for (int o = 16; o; o >>= 1) s += __shfl_xor_sync(0xffffffffu, s, o);
    float mu = s * (1.f / 256.f);
    float vs = 0.f;
    #pragma unroll
    for (int i = 0; i < 8; ++i) { float d = v[i] - mu; vs += d * d; }
    #pragma unroll
    for (int o = 16; o; o >>= 1) vs += __shfl_xor_sync(0xffffffffu, vs, o);
    float inv = rsqrtf(vs * (1.f / 256.f) + 1e-5f);

    float hn[8];
    #pragma unroll
    for (int i = 0; i < 8; ++i)
        hn[i] = (v[i] - mu) * inv * lng[lane + 32 * i] + lnb[lane + 32 * i];

    #pragma unroll
    for (int j = 0; j < NACT; ++j) {
        float p = 0.f;
        #pragma unroll
        for (int i = 0; i < 8; ++i) p = fmaf(hn[i], W2[j * RDIM + lane + 32 * i], p);
        #pragma unroll
        for (int o = 16; o; o >>= 1) p += __shfl_xor_sync(0xffffffffu, p, o);
        if (lane == j) q[(size_t)warp * NACT + j] = p + b2[j];
    }
}

// ---------------------------------------------------------------------------
extern "C" void kernel_launch(void* const* d_in, const int* in_sizes, int n_in,
                              void* d_out, int out_size)
{
    const float* inputs = (const float*)d_in[0];
    const float* hidden = (const float*)d_in[1];
    const int*   mask   = (const int*)  d_in[2];
    const float* Wfc    = (const float*)d_in[3];
    const float* bfc    = (const float*)d_in[4];
    const float* Wh     = (const float*)d_in[5];
    const float* asrc   = (const float*)d_in[6];
    const float* adst   = (const float*)d_in[7];
    const float* Wo     = (const float*)d_in[8];
    const float* bo     = (const float*)d_in[9];
    const float* W1     = (const float*)d_in[10];
    const float* b1     = (const float*)d_in[11];
    const float* Wih    = (const float*)d_in[12];
    const float* Whh    = (const float*)d_in[13];
    const float* bih    = (const float*)d_in[14];
    const float* bhh    = (const float*)d_in[15];
    const float* lng    = (const float*)d_in[16];
    const float* lnb    = (const float*)d_in[17];
    const float* W2     = (const float*)d_in[18];
    const float* b2     = (const float*)d_in[19];

    const int B = in_sizes[0] / (AN * OBS);       // 4096
    const int nrows = B * AN;                     // 131072

    float* q_out  = (float*)d_out;                        // [B*A, 16]
    float* hh_out = (float*)d_out + (size_t)nrows * NACT; // [B*A, 256]

    float* xr_ptr = nullptr;
    cudaGetSymbolAddress((void**)&xr_ptr, g_xr);

    cudaFuncSetAttribute(k1_gat_fc1, cudaFuncAttributeMaxDynamicSharedMemorySize, SMEM1);
    cudaFuncSetAttribute(k2_gru,     cudaFuncAttributeMaxDynamicSharedMemorySize, SMEM2);

    k1_gat_fc1<<<B, 256, SMEM1>>>(inputs, mask, Wfc, bfc, Wh, asrc, adst,
                                  Wo, bo, W1, b1, xr_ptr);
    k2_gru<<<dim3(nrows / 32, 4), 256, SMEM2>>>(xr_ptr, hidden, Wih, Whh,
                                                bih, bhh, hh_out);
    k3_ln_fc2<<<(nrows + 7) / 8, 256>>>(hh_out, lng, lnb, W2, b2, q_out, nrows);
}

// round 2
// speedup vs baseline: 1.0020x; 1.0020x over previous
#include <cuda_runtime.h>
#include <cuda_bf16.h>

// Problem constants
#define AN   32      // agents
#define OBS  128
#define EDIM 64
#define DDIM 64
#define HHEADS 4
#define RDIM 256
#define NACT 16
#define ZDIM 192     // OBS + EDIM
#define MAXROWS (4096*32)

// Scratch: XR = relu(fc1([inputs, att]))  [B*A, 256]
__device__ float g_xr[MAXROWS * RDIM];

__device__ __forceinline__ float sigf(float x) { return 1.0f / (1.0f + __expf(-x)); }

// ---------------------------------------------------------------------------
// Kernel 1: per-batch GAT + fc1  (one CTA per batch element b, 256 threads)
// ---------------------------------------------------------------------------
// smem layout (bytes):
//  [0      ,16384)  X[32][128]
//  [16384  ,24576)  xe[32][64]
//  [24576  ,57856)  bufA: WfcT[128][65]  then  hsm[4][32][64]
//  [57856  ,58368)  ssrc[128]
//  [58368  ,58880)  sdst[128]
//  [58880  ,62976)  msk[32][32] (int)
//  [62976  ,79360)  alpha[4][32][32]  then  att[32][64]
//  [79360  ,112256) bufB: agg[32][256]  then  f1T[32][257]
#define SMEM1 112256

__global__ void __launch_bounds__(256) k1_gat_fc1(
    const float* __restrict__ inputs, const int* __restrict__ mask,
    const float* __restrict__ Wfc, const float* __restrict__ bfc,
    const float* __restrict__ Wh,  const float* __restrict__ asrc,
    const float* __restrict__ adst,const float* __restrict__ Wo,
    const float* __restrict__ bo,  const float* __restrict__ W1,
    const float* __restrict__ b1,  float* __restrict__ xr_out)
{
    extern __shared__ char sm[];
    float* X    = (float*)(sm);
    float* xe   = (float*)(sm + 16384);
    float* bufA = (float*)(sm + 24576);
    float* ssrc = (float*)(sm + 57856);
    float* sdst = (float*)(sm + 58368);
    int*   msk  = (int*)  (sm + 58880);
    float* alpha= (float*)(sm + 62976);
    float* att  = alpha;                  // overlays alpha after it is dead
    float* bufB = (float*)(sm + 79360);

    const int tid = threadIdx.x;
    const int b   = blockIdx.x;

    // ---- load inputs, mask, transposed gat_fc weight ----
    const float* inb = inputs + (size_t)b * (AN * OBS);
    for (int i = tid; i < AN * OBS; i += 256) X[i] = inb[i];
    for (int i = tid; i < AN * AN;  i += 256) msk[i] = mask[(size_t)b * AN * AN + i];
    for (int i = tid; i < EDIM * OBS; i += 256) {
        int e = i >> 7, o = i & 127;
        bufA[o * 65 + e] = Wfc[i];        // WfcT[o][e], pitch 65 (conflict-free)
    }
    __syncthreads();

    // ---- S1: xe = X @ Wfc^T + bfc   [32,64] ----
    for (int out = tid; out < AN * EDIM; out += 256) {
        int a = out >> 6, e = out & 63;
        float acc = bfc[e];
        const float* xrow = X + a * OBS;
        #pragma unroll 8
        for (int o = 0; o < OBS; ++o) acc = fmaf(xrow[o], bufA[o * 65 + e], acc);
        xe[out] = acc;
    }
    __syncthreads();

    // ---- S2: h[hd][a][d] = xe @ W_h   (overwrites bufA) ----
    float* hsm = bufA;
    for (int out = tid; out < HHEADS * AN * DDIM; out += 256) {
        int d = out & 63, a = (out >> 6) & 31, hd = out >> 11;
        float acc = 0.f;
        const float* xr_ = xe + a * 64;
        const float* wp  = Wh + (size_t)hd * EDIM * DDIM + d;
        #pragma unroll 8
        for (int e = 0; e < EDIM; ++e) acc = fmaf(xr_[e], wp[e * 64], acc);
        hsm[(hd * 32 + a) * 64 + d] = acc;
    }
    __syncthreads();

    // ---- s_src / s_dst: one warp per group of rows ----
    {
        int warp = tid >> 5, lane = tid & 31;
        for (int row = warp; row < HHEADS * AN; row += 8) {
            int hd = row >> 5;
            const float* hr = hsm + row * 64;
            float vs = hr[lane] * asrc[hd * 64 + lane] + hr[lane + 32] * asrc[hd * 64 + lane + 32];
            float vd = hr[lane] * adst[hd * 64 + lane] + hr[lane + 32] * adst[hd * 64 + lane + 32];
            #pragma unroll
            for (int o = 16; o; o >>= 1) {
                vs += __shfl_xor_sync(0xffffffffu, vs, o);
                vd += __shfl_xor_sync(0xffffffffu, vd, o);
            }
            if (lane == 0) { ssrc[row] = vs; sdst[row] = vd; }
        }
    }
    __syncthreads();

    // ---- S3: masked-softmax attention weights alpha[hd][i][j] ----
    if (tid < HHEADS * AN) {
        int hd = tid >> 5, i = tid & 31;
        float si = ssrc[tid];
        float v[32];
        float m = -3.4e38f;
        #pragma unroll
        for (int j = 0; j < 32; ++j) {
            float e_ = si + sdst[hd * 32 + j];
            float l  = e_ > 0.f ? e_ : 0.2f * e_;           // leaky_relu(0.2)
            if (msk[i * 32 + j] <= 0) l = -1e9f;
            v[j] = l; m = fmaxf(m, l);
        }
        float s = 0.f;
        #pragma unroll
        for (int j = 0; j < 32; ++j) { v[j] = __expf(v[j] - m); s += v[j]; }
        float inv = 1.f / s;
        #pragma unroll
        for (int j = 0; j < 32; ++j) alpha[tid * 32 + j] = v[j] * inv;
    }
    __syncthreads();

    // ---- S4: agg[a][hd*64+d] = alpha @ h  (into bufB) ----
    float* agg = bufB;
    for (int out = tid; out < AN * HHEADS * DDIM; out += 256) {
        int d = out & 63, hd = (out >> 6) & 3, a = out >> 8;
        const float* al = alpha + (hd * 32 + a) * 32;
        const float* hj = hsm + (hd * 32) * 64 + d;
        float acc = 0.f;
        #pragma unroll
        for (int j = 0; j < 32; ++j) acc = fmaf(al[j], hj[j * 64], acc);
        agg[a * 256 + hd * 64 + d] = acc;
    }
    __syncthreads();

    // ---- S5: att = agg @ W_o + b_o  (overlays alpha) ----
    for (int out = tid; out < AN * EDIM; out += 256) {
        int a = out >> 6, e = out & 63;
        float acc = bo[e];
        const float* ag = agg + a * 256;
        const float* wp = Wo + e;
        #pragma unroll 8
        for (int k = 0; k < 256; ++k) acc = fmaf(ag[k], wp[k * 64], acc);
        att[a * 64 + e] = acc;
    }
    __syncthreads();

    // ---- S6: xr = relu([X, att] @ fc1_w^T + fc1_b) ----
    // thread tid owns output column r = tid for all 32 rows (a).
    float* f1T = bufB;   // [32][257]  (overlays agg)
    float acc[32];
    {
        float bb = b1[tid];
        #pragma unroll
        for (int a = 0; a < 32; ++a) acc[a] = bb;
    }
    for (int kt = 0; kt < 6; ++kt) {
        __syncthreads();
        for (int idx = tid; idx < 256 * 32; idx += 256) {
            int kk = idx & 31, r = idx >> 5;
            f1T[kk * 257 + r] = W1[r * ZDIM + kt * 32 + kk];
        }
        __syncthreads();
        const float* zb; int pitch;
        if (kt < 4) { zb = X + kt * 32;        pitch = OBS; }
        else        { zb = att + (kt - 4) * 32; pitch = 64; }
        #pragma unroll
        for (int kkg = 0; kkg < 8; ++kkg) {
            float w0 = f1T[(kkg * 4 + 0) * 257 + tid];
            float w1 = f1T[(kkg * 4 + 1) * 257 + tid];
            float w2 = f1T[(kkg * 4 + 2) * 257 + tid];
            float w3 = f1T[(kkg * 4 + 3) * 257 + tid];
            #pragma unroll
            for (int a = 0; a < 32; ++a) {
                const float4 u = *(const float4*)(zb + a * pitch + kkg * 4);
                acc[a] = fmaf(u.x, w0, fmaf(u.y, w1, fmaf(u.z, w2, fmaf(u.w, w3, acc[a]))));
            }
        }
    }
    {
        size_t rowbase = (size_t)b * 32;
        #pragma unroll
        for (int a = 0; a < 32; ++a)
            xr_out[(rowbase + a) * RDIM + tid] = fmaxf(acc[a], 0.f);
    }
}

// ---------------------------------------------------------------------------
// Kernel 2: fused GRU GEMM + gates -> hh
// grid = (B*A/32, 4);  CTA tile = 32 rows x 64 gate-columns, 256 threads
// ---------------------------------------------------------------------------
// smem: UT[512][36] transposed [xr | h] (73728 B) + Wt[3][32][65] (24960 B)
#define SMEM2 (73728 + 24960)

__global__ void __launch_bounds__(256, 2) k2_gru(
    const float* __restrict__ xr,  const float* __restrict__ hin,
    const float* __restrict__ Wih, const float* __restrict__ Whh,
    const float* __restrict__ bih, const float* __restrict__ bhh,
    float* __restrict__ hh_out)
{
    extern __shared__ float smf[];
    float* UT = smf;                 // [512][36]
    float* Wt = smf + 512 * 36;      // [3][32][65]

    const int tid = threadIdx.x;
    const int tx  = tid & 63;        // gate column within span
    const int ty  = tid >> 6;        // row group (8 rows each)
    const size_t r0 = (size_t)blockIdx.x * 32;
    const int c0 = blockIdx.y * 64;

    // load transposed activations: UT[k][rr]; k<256 = xr, k>=256 = h_in
    for (int idx = tid; idx < 32 * 256; idx += 256) {
        int k = idx & 255, rr = idx >> 8;
        UT[k * 36 + rr]          = xr [(r0 + rr) * RDIM + k];
        UT[(256 + k) * 36 + rr]  = hin[(r0 + rr) * RDIM + k];
    }

    float acc[2][8][3];
    #pragma unroll
    for (int p = 0; p < 2; ++p)
        #pragma unroll
        for (int j = 0; j < 8; ++j)
            #pragma unroll
            for (int g = 0; g < 3; ++g) acc[p][j][g] = 0.f;

    #pragma unroll
    for (int ph = 0; ph < 2; ++ph) {
        const float* W = (ph == 0) ? Wih : Whh;
        for (int kt = 0; kt < 8; ++kt) {
            __syncthreads();
            // stage weight tile: rows {c, 256+c, 512+c} for c in [c0,c0+64), k-tile of 32
            for (int idx = tid; idx < 6144; idx += 256) {
                int kk = idx & 31, cl = (idx >> 5) & 63, g = idx >> 11;
                Wt[g * 2080 + kk * 65 + cl] = W[(size_t)(g * 256 + c0 + cl) * 256 + (kt << 5) + kk];
            }
            __syncthreads();
            int kb = ph * 256 + kt * 32;
            #pragma unroll
            for (int kk = 0; kk < 32; ++kk) {
                const float* up = &UT[(kb + kk) * 36 + ty * 8];
                float4 ua = *(const float4*)up;
                float4 ub = *(const float4*)(up + 4);
                float u[8] = {ua.x, ua.y, ua.z, ua.w, ub.x, ub.y, ub.z, ub.w};
                float w0 = Wt[           kk * 65 + tx];
                float w1 = Wt[1 * 2080 + kk * 65 + tx];
                float w2 = Wt[2 * 2080 + kk * 65 + tx];
                #pragma unroll
                for (int j = 0; j < 8; ++j) {
                    acc[ph][j][0] = fmaf(u[j], w0, acc[ph][j][0]);
                    acc[ph][j][1] = fmaf(u[j], w1, acc[ph][j][1]);
                    acc[ph][j][2] = fmaf(u[j], w2, acc[ph][j][2]);
                }
            }
        }
    }

    // gates + output (UT still holds h_in for hprev)
    const int c = c0 + tx;
    const float bi_r = bih[c], bi_z = bih[256 + c], bi_n = bih[512 + c];
    const float bh_r = bhh[c], bh_z = bhh[256 + c], bh_n = bhh[512 + c];
    #pragma unroll
    for (int j = 0; j < 8; ++j) {
        size_t row = r0 + ty * 8 + j;
        float hprev = UT[(256 + c) * 36 + ty * 8 + j];
        float rg = sigf(acc[0][j][0] + bi_r + acc[1][j][0] + bh_r);
        float zg = sigf(acc[0][j][1] + bi_z + acc[1][j][1] + bh_z);
        float ng = tanhf(acc[0][j][2] + bi_n + rg * (acc[1][j][2] + bh_n));
        hh_out[row * RDIM + c] = (1.f - zg) * ng + zg * hprev;
    }
}

// ---------------------------------------------------------------------------
// Kernel 3: LayerNorm + fc2 (one warp per row)
// ---------------------------------------------------------------------------
__global__ void __launch_bounds__(256) k3_ln_fc2(
    const float* __restrict__ hh, const float* __restrict__ lng,
    const float* __restrict__ lnb, const float* __restrict__ W2,
    const float* __restrict__ b2, float* __restrict__ q, int nrows)
{
    int warp = (blockIdx.x * blockDim.x + threadIdx.x) >> 5;
    int lane = threadIdx.x & 31;
    if (warp >= nrows) return;
    const float* hr = hh + (size_t)warp * RDIM;

    float v[8];
    float s = 0.f;
    #pragma unroll
    for (int i = 0; i < 8; ++i) { v[i] = hr[lane + 32 * i]; s += v[i]; }
    #pragma unroll
    for (int o = 16; o; o >>= 1) s += __shfl_xor_sync(0xffffffffu, s, o);
    float mu = s * (1.f / 256.f);
    float vs = 0.f;
    #pragma unroll
    for (int i = 0; i < 8; ++i) { float d = v[i] - mu; vs += d * d; }
    #pragma unroll
    for (int o = 16; o; o >>= 1) vs += __shfl_xor_sync(0xffffffffu, vs, o);
    float inv = rsqrtf(vs * (1.f / 256.f) + 1e-5f);

    float hn[8];
    #pragma unroll
    for (int i = 0; i < 8; ++i)
        hn[i] = (v[i] - mu) * inv * lng[lane + 32 * i] + lnb[lane + 32 * i];

    #pragma unroll
    for (int j = 0; j < NACT; ++j) {
        float p = 0.f;
        #pragma unroll
        for (int i = 0; i < 8; ++i) p = fmaf(hn[i], W2[j * RDIM + lane + 32 * i], p);
        #pragma unroll
        for (int o = 16; o; o >>= 1) p += __shfl_xor_sync(0xffffffffu, p, o);
        if (lane == j) q[(size_t)warp * NACT + j] = p + b2[j];
    }
}

// ---------------------------------------------------------------------------
extern "C" void kernel_launch(void* const* d_in, const int* in_sizes, int n_in,
                              void* d_out, int out_size)
{
    const float* inputs = (const float*)d_in[0];
    const float* hidden = (const float*)d_in[1];
    const int*   mask   = (const int*)  d_in[2];
    const float* Wfc    = (const float*)d_in[3];
    const float* bfc    = (const float*)d_in[4];
    const float* Wh     = (const float*)d_in[5];
    const float* asrc   = (const float*)d_in[6];
    const float* adst   = (const float*)d_in[7];
    const float* Wo     = (const float*)d_in[8];
    const float* bo     = (const float*)d_in[9];
    const float* W1     = (const float*)d_in[10];
    const float* b1     = (const float*)d_in[11];
    const float* Wih    = (const float*)d_in[12];
    const float* Whh    = (const float*)d_in[13];
    const float* bih    = (const float*)d_in[14];
    const float* bhh    = (const float*)d_in[15];
    const float* lng    = (const float*)d_in[16];
    const float* lnb    = (const float*)d_in[17];
    const float* W2     = (const float*)d_in[18];
    const float* b2     = (const float*)d_in[19];

    const int B = in_sizes[0] / (AN * OBS);       // 4096
    const int nrows = B * AN;                     // 131072

    float* q_out  = (float*)d_out;                        // [B*A, 16]
    float* hh_out = (float*)d_out + (size_t)nrows * NACT; // [B*A, 256]

    float* xr_ptr = nullptr;
    cudaGetSymbolAddress((void**)&xr_ptr, g_xr);

    cudaFuncSetAttribute(k1_gat_fc1, cudaFuncAttributeMaxDynamicSharedMemorySize, SMEM1);
    cudaFuncSetAttribute(k2_gru,     cudaFuncAttributeMaxDynamicSharedMemorySize, SMEM2);

    k1_gat_fc1<<<B, 256, SMEM1>>>(inputs, mask, Wfc, bfc, Wh, asrc, adst,
                                  Wo, bo, W1, b1, xr_ptr);
    k2_gru<<<dim3(nrows / 32, 4), 256, SMEM2>>>(xr_ptr, hidden, Wih, Whh,
                                                bih, bhh, hh_out);
    k3_ln_fc2<<<(nrows + 7) / 8, 256>>>(hh_out, lng, lnb, W2, b2, q_out, nrows);
}

// round 3
// speedup vs baseline: 1.7228x; 1.7193x over previous
#include <cuda_runtime.h>
#include <cuda_bf16.h>
#include <stdint.h>

// Problem constants
#define AN   32      // agents
#define OBS  128
#define EDIM 64
#define DDIM 64
#define HHEADS 4
#define RDIM 256
#define NACT 16
#define ZDIM 192     // OBS + EDIM
#define MAXROWS (4096*32)

// Scratch: XR = relu(fc1([inputs, att]))  [B*A, 256]
__device__ float g_xr[MAXROWS * RDIM];

__device__ __forceinline__ float sigf(float x) { return 1.0f / (1.0f + __expf(-x)); }

__device__ __forceinline__ uint32_t f2tf(float x) {
    uint32_t r;
    asm("cvt.rna.tf32.f32 %0, %1;" : "=r"(r) : "f"(x));
    return r;
}

#define MMA_TF32(d, a, b)                                                     \
    asm volatile(                                                             \
        "mma.sync.aligned.m16n8k8.row.col.f32.tf32.tf32.f32 "                 \
        "{%0,%1,%2,%3},{%4,%5,%6,%7},{%8,%9},{%0,%1,%2,%3};"                  \
        : "+f"(d[0]), "+f"(d[1]), "+f"(d[2]), "+f"(d[3])                      \
        : "r"(a[0]), "r"(a[1]), "r"(a[2]), "r"(a[3]), "r"(b[0]), "r"(b[1]))

// ---------------------------------------------------------------------------
// Kernel 1: per-batch GAT + fc1  (one CTA per batch element b, 256 threads)
// ---------------------------------------------------------------------------
#define SMEM1 112256

__global__ void __launch_bounds__(256) k1_gat_fc1(
    const float* __restrict__ inputs, const int* __restrict__ mask,
    const float* __restrict__ Wfc, const float* __restrict__ bfc,
    const float* __restrict__ Wh,  const float* __restrict__ asrc,
    const float* __restrict__ adst,const float* __restrict__ Wo,
    const float* __restrict__ bo,  const float* __restrict__ W1,
    const float* __restrict__ b1,  float* __restrict__ xr_out)
{
    extern __shared__ char sm[];
    float* X    = (float*)(sm);
    float* xe   = (float*)(sm + 16384);
    float* bufA = (float*)(sm + 24576);
    float* ssrc = (float*)(sm + 57856);
    float* sdst = (float*)(sm + 58368);
    int*   msk  = (int*)  (sm + 58880);
    float* alpha= (float*)(sm + 62976);
    float* att  = alpha;
    float* bufB = (float*)(sm + 79360);

    const int tid = threadIdx.x;
    const int b   = blockIdx.x;

    const float* inb = inputs + (size_t)b * (AN * OBS);
    for (int i = tid; i < AN * OBS; i += 256) X[i] = inb[i];
    for (int i = tid; i < AN * AN;  i += 256) msk[i] = mask[(size_t)b * AN * AN + i];
    for (int i = tid; i < EDIM * OBS; i += 256) {
        int e = i >> 7, o = i & 127;
        bufA[o * 65 + e] = Wfc[i];
    }
    __syncthreads();

    for (int out = tid; out < AN * EDIM; out += 256) {
        int a = out >> 6, e = out & 63;
        float acc = bfc[e];
        const float* xrow = X + a * OBS;
        #pragma unroll 8
        for (int o = 0; o < OBS; ++o) acc = fmaf(xrow[o], bufA[o * 65 + e], acc);
        xe[out] = acc;
    }
    __syncthreads();

    float* hsm = bufA;
    for (int out = tid; out < HHEADS * AN * DDIM; out += 256) {
        int d = out & 63, a = (out >> 6) & 31, hd = out >> 11;
        float acc = 0.f;
        const float* xr_ = xe + a * 64;
        const float* wp  = Wh + (size_t)hd * EDIM * DDIM + d;
        #pragma unroll 8
        for (int e = 0; e < EDIM; ++e) acc = fmaf(xr_[e], wp[e * 64], acc);
        hsm[(hd * 32 + a) * 64 + d] = acc;
    }
    __syncthreads();

    {
        int warp = tid >> 5, lane = tid & 31;
        for (int row = warp; row < HHEADS * AN; row += 8) {
            int hd = row >> 5;
            const float* hr = hsm + row * 64;
            float vs = hr[lane] * asrc[hd * 64 + lane] + hr[lane + 32] * asrc[hd * 64 + lane + 32];
            float vd = hr[lane] * adst[hd * 64 + lane] + hr[lane + 32] * adst[hd * 64 + lane + 32];
            #pragma unroll
            for (int o = 16; o; o >>= 1) {
                vs += __shfl_xor_sync(0xffffffffu, vs, o);
                vd += __shfl_xor_sync(0xffffffffu, vd, o);
            }
            if (lane == 0) { ssrc[row] = vs; sdst[row] = vd; }
        }
    }
    __syncthreads();

    if (tid < HHEADS * AN) {
        int hd = tid >> 5, i = tid & 31;
        float si = ssrc[tid];
        float v[32];
        float m = -3.4e38f;
        #pragma unroll
        for (int j = 0; j < 32; ++j) {
            float e_ = si + sdst[hd * 32 + j];
            float l  = e_ > 0.f ? e_ : 0.2f * e_;
            if (msk[i * 32 + j] <= 0) l = -1e9f;
            v[j] = l; m = fmaxf(m, l);
        }
        float s = 0.f;
        #pragma unroll
        for (int j = 0; j < 32; ++j) { v[j] = __expf(v[j] - m); s += v[j]; }
        float inv = 1.f / s;
        #pragma unroll
        for (int j = 0; j < 32; ++j) alpha[tid * 32 + j] = v[j] * inv;
    }
    __syncthreads();

    float* agg = bufB;
    for (int out = tid; out < AN * HHEADS * DDIM; out += 256) {
        int d = out & 63, hd = (out >> 6) & 3, a = out >> 8;
        const float* al = alpha + (hd * 32 + a) * 32;
        const float* hj = hsm + (hd * 32) * 64 + d;
        float acc = 0.f;
        #pragma unroll
        for (int j = 0; j < 32; ++j) acc = fmaf(al[j], hj[j * 64], acc);
        agg[a * 256 + hd * 64 + d] = acc;
    }
    __syncthreads();

    for (int out = tid; out < AN * EDIM; out += 256) {
        int a = out >> 6, e = out & 63;
        float acc = bo[e];
        const float* ag = agg + a * 256;
        const float* wp = Wo + e;
        #pragma unroll 8
        for (int k = 0; k < 256; ++k) acc = fmaf(ag[k], wp[k * 64], acc);
        att[a * 64 + e] = acc;
    }
    __syncthreads();

    float* f1T = bufB;
    float acc[32];
    {
        float bb = b1[tid];
        #pragma unroll
        for (int a = 0; a < 32; ++a) acc[a] = bb;
    }
    for (int kt = 0; kt < 6; ++kt) {
        __syncthreads();
        for (int idx = tid; idx < 256 * 32; idx += 256) {
            int kk = idx & 31, r = idx >> 5;
            f1T[kk * 257 + r] = W1[r * ZDIM + kt * 32 + kk];
        }
        __syncthreads();
        const float* zb; int pitch;
        if (kt < 4) { zb = X + kt * 32;        pitch = OBS; }
        else        { zb = att + (kt - 4) * 32; pitch = 64; }
        #pragma unroll
        for (int kkg = 0; kkg < 8; ++kkg) {
            float w0 = f1T[(kkg * 4 + 0) * 257 + tid];
            float w1 = f1T[(kkg * 4 + 1) * 257 + tid];
            float w2 = f1T[(kkg * 4 + 2) * 257 + tid];
            float w3 = f1T[(kkg * 4 + 3) * 257 + tid];
            #pragma unroll
            for (int a = 0; a < 32; ++a) {
                const float4 u = *(const float4*)(zb + a * pitch + kkg * 4);
                acc[a] = fmaf(u.x, w0, fmaf(u.y, w1, fmaf(u.z, w2, fmaf(u.w, w3, acc[a]))));
            }
        }
    }
    {
        size_t rowbase = (size_t)b * 32;
        #pragma unroll
        for (int a = 0; a < 32; ++a)
            xr_out[(rowbase + a) * RDIM + tid] = fmaxf(acc[a], 0.f);
    }
}

// ---------------------------------------------------------------------------
// Kernel 2: GRU via tf32 tensor-core GEMM + fused gates
//
// Logical GEMM: acc[row][q] = sum_k U[row][k] * W'[q][k],  K = 512 (xr | h)
// q-space (128 per CTA, for 32 output cols): [0,32)=r(Wih+Whh), [32,64)=z,
// [64,96)=n_i (Wih half, zero for k>=256), [96,128)=n_h (Whh half, zero k<256)
//
// CTA: 128 rows x 128 q, 8 warps (warp tile 32x64), BK=16, double buffered,
// XOR-swizzled smem staging (pitch 136). Epilogue recombines gates via smem.
// ---------------------------------------------------------------------------
#define K2_SMEM 68096   // max(staging 34816, Sacc 128*133*4 = 68096)

__global__ void __launch_bounds__(256, 2) k2_gru_tc(
    const float* __restrict__ xr,  const float* __restrict__ hin,
    const float* __restrict__ Wih, const float* __restrict__ Whh,
    const float* __restrict__ bih, const float* __restrict__ bhh,
    float* __restrict__ hh_out)
{
    extern __shared__ uint32_t sm2[];
    uint32_t* As = sm2;                  // [2][16][136] tf32
    uint32_t* Bs = sm2 + 2 * 16 * 136;   // [2][16][136] tf32

    const int tid  = threadIdx.x;
    const int lane = tid & 31;
    const int warp = tid >> 5;
    const int wm = (warp & 3) * 32;      // warp row offset
    const int wn = (warp >> 2) * 64;     // warp q offset
    const int g  = lane >> 2;
    const int tg = lane & 3;
    const size_t r0 = (size_t)blockIdx.y * 128;
    const int c0 = blockIdx.x * 32;

    // staging index: id = tid + 256*i -> m/q = id>>2 (0..127), kq = (id&3)*4
    const int m0i = tid >> 2;
    const int kqA = (tid & 3) * 4;

    float4 ra[2], rb[2];

    float acc[2][8][4];
    #pragma unroll
    for (int mt = 0; mt < 2; ++mt)
        #pragma unroll
        for (int nt = 0; nt < 8; ++nt)
            #pragma unroll
            for (int e = 0; e < 4; ++e) acc[mt][nt][e] = 0.f;

    auto ldg_stage = [&](int s) {
        const int kb = s * 16;
        const int kbl = kb & 255;
        const float* srcA = (kb < 256) ? xr : hin;
        const float* srcW = (kb < 256) ? Wih : Whh;
        #pragma unroll
        for (int i = 0; i < 2; ++i) {
            int m = m0i + i * 64;
            ra[i] = *(const float4*)(srcA + (r0 + m) * 256 + kbl + kqA);
            int grp = m >> 5, cl = c0 + (m & 31);
            bool zero = (kb < 256) ? (grp == 3) : (grp == 2);
            int wrow = (grp == 0) ? cl : (grp == 1) ? 256 + cl : 512 + cl;
            if (zero) rb[i] = make_float4(0.f, 0.f, 0.f, 0.f);
            else      rb[i] = *(const float4*)(srcW + (size_t)wrow * 256 + kbl + kqA);
        }
    };

    auto sts_stage = [&](int buf) {
        uint32_t* Ab = As + buf * (16 * 136);
        uint32_t* Bb = Bs + buf * (16 * 136);
        #pragma unroll
        for (int i = 0; i < 2; ++i) {
            int m = m0i + i * 64;
            float va[4] = {ra[i].x, ra[i].y, ra[i].z, ra[i].w};
            float vb[4] = {rb[i].x, rb[i].y, rb[i].z, rb[i].w};
            #pragma unroll
            for (int j = 0; j < 4; ++j) {
                int k  = kqA + j;
                int sw = ((k >> 2) & 3) << 3;
                Ab[k * 136 + (m ^ sw)] = f2tf(va[j]);
                Bb[k * 136 + (m ^ sw)] = f2tf(vb[j]);
            }
        }
    };

    auto compute_stage = [&](int buf) {
        const uint32_t* Ab = As + buf * (16 * 136);
        const uint32_t* Bb = Bs + buf * (16 * 136);
        #pragma unroll
        for (int k8 = 0; k8 < 2; ++k8) {
            const int kk = k8 * 8;
            const int s0 = ((2 * k8) & 3) << 3;
            const int s1 = ((2 * k8 + 1) & 3) << 3;
            uint32_t a[2][4];
            #pragma unroll
            for (int mt = 0; mt < 2; ++mt) {
                int m0 = wm + mt * 16;
                a[mt][0] = Ab[(kk + tg) * 136 + ((m0 + g) ^ s0)];
                a[mt][1] = Ab[(kk + tg) * 136 + ((m0 + g + 8) ^ s0)];
                a[mt][2] = Ab[(kk + tg + 4) * 136 + ((m0 + g) ^ s1)];
                a[mt][3] = Ab[(kk + tg + 4) * 136 + ((m0 + g + 8) ^ s1)];
            }
            uint32_t bf[8][2];
            #pragma unroll
            for (int nt = 0; nt < 8; ++nt) {
                int q0 = wn + nt * 8 + g;
                bf[nt][0] = Bb[(kk + tg) * 136 + (q0 ^ s0)];
                bf[nt][1] = Bb[(kk + tg + 4) * 136 + (q0 ^ s1)];
            }
            #pragma unroll
            for (int mt = 0; mt < 2; ++mt)
                #pragma unroll
                for (int nt = 0; nt < 8; ++nt)
                    MMA_TF32(acc[mt][nt], a[mt], bf[nt]);
        }
    };

    // pipeline: 32 stages of BK=16
    ldg_stage(0);
    sts_stage(0);
    __syncthreads();
    int buf = 0;
    for (int s = 0; s < 32; ++s) {
        if (s < 31) ldg_stage(s + 1);
        compute_stage(buf);
        if (s < 31) {
            sts_stage(buf ^ 1);
            __syncthreads();
            buf ^= 1;
        }
    }
    __syncthreads();

    // epilogue: stage accumulators to smem (q-major, pitch 133 = conflict-free)
    float* Sacc = (float*)sm2;
    #pragma unroll
    for (int mt = 0; mt < 2; ++mt) {
        #pragma unroll
        for (int nt = 0; nt < 8; ++nt) {
            int rl = wm + mt * 16 + g;
            int q  = wn + nt * 8 + tg * 2;
            Sacc[q * 133 + rl]           = acc[mt][nt][0];
            Sacc[(q + 1) * 133 + rl]     = acc[mt][nt][1];
            Sacc[q * 133 + rl + 8]       = acc[mt][nt][2];
            Sacc[(q + 1) * 133 + rl + 8] = acc[mt][nt][3];
        }
    }
    __syncthreads();

    // gate math: thread -> (col = tid&31, 16 rows)
    const int col = tid & 31;
    const int c   = c0 + col;
    const int rg0 = (tid >> 5) * 16;
    const float br  = bih[c] + bhh[c];
    const float bz  = bih[256 + c] + bhh[256 + c];
    const float bni = bih[512 + c];
    const float bnh = bhh[512 + c];
    #pragma unroll
    for (int j = 0; j < 16; ++j) {
        int rl = rg0 + j;
        float gr  = Sacc[col * 133 + rl];
        float gz  = Sacc[(32 + col) * 133 + rl];
        float gni = Sacc[(64 + col) * 133 + rl];
        float gnh = Sacc[(96 + col) * 133 + rl];
        float hprev = hin[(r0 + rl) * 256 + c];
        float rg_ = sigf(gr + br);
        float zg_ = sigf(gz + bz);
        float ng_ = tanhf(gni + bni + rg_ * (gnh + bnh));
        hh_out[(r0 + rl) * 256 + c] = (1.f - zg_) * ng_ + zg_ * hprev;
    }
}

// ---------------------------------------------------------------------------
// Kernel 3: LayerNorm + fc2 (one warp per row)
// ---------------------------------------------------------------------------
__global__ void __launch_bounds__(256) k3_ln_fc2(
    const float* __restrict__ hh, const float* __restrict__ lng,
    const float* __restrict__ lnb, const float* __restrict__ W2,
    const float* __restrict__ b2, float* __restrict__ q, int nrows)
{
    int warp = (blockIdx.x * blockDim.x + threadIdx.x) >> 5;
    int lane = threadIdx.x & 31;
    if (warp >= nrows) return;
    const float* hr = hh + (size_t)warp * RDIM;

    float v[8];
    float s = 0.f;
    #pragma unroll
    for (int i = 0; i < 8; ++i) { v[i] = hr[lane + 32 * i]; s += v[i]; }
    #pragma unroll
    for (int o = 16; o; o >>= 1) s += __shfl_xor_sync(0xffffffffu, s, o);
    float mu = s * (1.f / 256.f);
    float vs = 0.f;
    #pragma unroll
    for (int i = 0; i < 8; ++i) { float d = v[i] - mu; vs += d * d; }
    #pragma unroll
    for (int o = 16; o; o >>= 1) vs += __shfl_xor_sync(0xffffffffu, vs, o);
    float inv = rsqrtf(vs * (1.f / 256.f) + 1e-5f);

    float hn[8];
    #pragma unroll
    for (int i = 0; i < 8; ++i)
        hn[i] = (v[i] - mu) * inv * lng[lane + 32 * i] + lnb[lane + 32 * i];

    #pragma unroll
    for (int j = 0; j < NACT; ++j) {
        float p = 0.f;
        #pragma unroll
        for (int i = 0; i < 8; ++i) p = fmaf(hn[i], W2[j * RDIM + lane + 32 * i], p);
        #pragma unroll
        for (int o = 16; o; o >>= 1) p += __shfl_xor_sync(0xffffffffu, p, o);
        if (lane == j) q[(size_t)warp * NACT + j] = p + b2[j];
    }
}

// ---------------------------------------------------------------------------
extern "C" void kernel_launch(void* const* d_in, const int* in_sizes, int n_in,
                              void* d_out, int out_size)
{
    const float* inputs = (const float*)d_in[0];
    const float* hidden = (const float*)d_in[1];
    const int*   mask   = (const int*)  d_in[2];
    const float* Wfc    = (const float*)d_in[3];
    const float* bfc    = (const float*)d_in[4];
    const float* Wh     = (const float*)d_in[5];
    const float* asrc   = (const float*)d_in[6];
    const float* adst   = (const float*)d_in[7];
    const float* Wo     = (const float*)d_in[8];
    const float* bo     = (const float*)d_in[9];
    const float* W1     = (const float*)d_in[10];
    const float* b1     = (const float*)d_in[11];
    const float* Wih    = (const float*)d_in[12];
    const float* Whh    = (const float*)d_in[13];
    const float* bih    = (const float*)d_in[14];
    const float* bhh    = (const float*)d_in[15];
    const float* lng    = (const float*)d_in[16];
    const float* lnb    = (const float*)d_in[17];
    const float* W2     = (const float*)d_in[18];
    const float* b2     = (const float*)d_in[19];

    const int B = in_sizes[0] / (AN * OBS);       // 4096
    const int nrows = B * AN;                     // 131072

    float* q_out  = (float*)d_out;                        // [B*A, 16]
    float* hh_out = (float*)d_out + (size_t)nrows * NACT; // [B*A, 256]

    float* xr_ptr = nullptr;
    cudaGetSymbolAddress((void**)&xr_ptr, g_xr);

    cudaFuncSetAttribute(k1_gat_fc1, cudaFuncAttributeMaxDynamicSharedMemorySize, SMEM1);
    cudaFuncSetAttribute(k2_gru_tc,  cudaFuncAttributeMaxDynamicSharedMemorySize, K2_SMEM);

    k1_gat_fc1<<<B, 256, SMEM1>>>(inputs, mask, Wfc, bfc, Wh, asrc, adst,
                                  Wo, bo, W1, b1, xr_ptr);
    // grid: col-blocks fastest so the 8 CTAs sharing an activation stripe are
    // L2-coresident (activation DRAM traffic ~8x lower than the transpose order)
    k2_gru_tc<<<dim3(8, nrows / 128), 256, K2_SMEM>>>(xr_ptr, hidden, Wih, Whh,
                                                      bih, bhh, hh_out);
    k3_ln_fc2<<<(nrows + 7) / 8, 256>>>(hh_out, lng, lnb, W2, b2, q_out, nrows);
}

// round 5
// speedup vs baseline: 3.4476x; 2.0012x over previous
#include <cuda_runtime.h>
#include <cuda_bf16.h>
#include <stdint.h>

// Problem constants
#define AN   32      // agents
#define OBS  128
#define EDIM 64
#define DDIM 64
#define HHEADS 4
#define RDIM 256
#define NACT 16
#define ZDIM 192     // OBS + EDIM
#define MAXROWS (4096*32)

// Scratch buffers (aliased across pipeline stages)
__device__ float g_buf64[MAXROWS * 64];    // XE -> ATT
__device__ float g_bufH [MAXROWS * RDIM];  // H
__device__ float g_bufG [MAXROWS * RDIM];  // agg -> XR
__device__ float g_WhT  [256 * 64];
__device__ float g_WoT  [64 * 256];

__device__ __forceinline__ float sigf(float x) { return 1.0f / (1.0f + __expf(-x)); }

__device__ __forceinline__ uint32_t f2tf(float x) {
    uint32_t r;
    asm("cvt.rna.tf32.f32 %0, %1;" : "=r"(r) : "f"(x));
    return r;
}

#define MMA_TF32(d, a, b)                                                     \
    asm volatile(                                                             \
        "mma.sync.aligned.m16n8k8.row.col.f32.tf32.tf32.f32 "                 \
        "{%0,%1,%2,%3},{%4,%5,%6,%7},{%8,%9},{%0,%1,%2,%3};"                  \
        : "+f"(d[0]), "+f"(d[1]), "+f"(d[2]), "+f"(d[3])                      \
        : "r"(a[0]), "r"(a[1]), "r"(a[2]), "r"(a[3]), "r"(b[0]), "r"(b[1]))

// ---------------------------------------------------------------------------
// k0: tiny transposes  WhT[h*64+d][e] = W_h[h][e][d];  WoT[e][k] = W_o[k][e]
// ---------------------------------------------------------------------------
__global__ void k0_prep(const float* __restrict__ Wh, const float* __restrict__ Wo,
                        float* __restrict__ WhT, float* __restrict__ WoT)
{
    int tid = blockIdx.x * blockDim.x + threadIdx.x;
    int stride = gridDim.x * blockDim.x;
    for (int i = tid; i < 256 * 64; i += stride) {
        int n = i >> 6, e = i & 63;
        int h = n >> 6, d = n & 63;
        WhT[i] = Wh[(h * 64 + e) * 64 + d];
    }
    for (int i = tid; i < 64 * 256; i += stride) {
        int e = i >> 8, k = i & 255;
        WoT[i] = Wo[k * 64 + e];
    }
}

// ---------------------------------------------------------------------------
// Generic tf32 GEMM:  C[M, N] = EPI( [A1|A2] @ W^T + bias )
//   A1: [M, K1], A2: [M, K2] (optional), W: [N, K1+K2] row-major.
//   CTA tile 128M x 64N, 8 warps (32x32 each), BK=16, double buffered.
//   EPI: 0 = none, 1 = +bias, 2 = relu(+bias)
// ---------------------------------------------------------------------------
#define GEMM_SMEM ((2*16*136 + 2*16*72) * 4)

template<int K1, int K2, int EPI>
__global__ void __launch_bounds__(256) gemm_tn(
    const float* __restrict__ A1, const float* __restrict__ A2,
    const float* __restrict__ W,  const float* __restrict__ bias,
    float* __restrict__ C)
{
    constexpr int KT = K1 + K2;
    constexpr int NS = KT / 16;
    extern __shared__ uint32_t sg[];
    uint32_t* As = sg;                   // [2][16][136]
    uint32_t* Bs = sg + 2 * 16 * 136;    // [2][16][72]

    const int tid  = threadIdx.x;
    const int lane = tid & 31;
    const int warp = tid >> 5;
    const int wm = (warp & 3) * 32;
    const int wn = (warp >> 2) * 32;
    const int g  = lane >> 2;
    const int tg = lane & 3;
    const size_t r0 = (size_t)blockIdx.y * 128;
    const int n0 = blockIdx.x * 64;
    const int ldc = gridDim.x * 64;

    const int m0i = tid >> 2;           // 0..63
    const int kq  = (tid & 3) * 4;

    float4 ra[2], rbv;

    float acc[2][4][4];
    #pragma unroll
    for (int mt = 0; mt < 2; ++mt)
        #pragma unroll
        for (int nt = 0; nt < 4; ++nt)
            #pragma unroll
            for (int e = 0; e < 4; ++e) acc[mt][nt][e] = 0.f;

    auto ldg_stage = [&](int s) {
        const int kb = s * 16;
        #pragma unroll
        for (int i = 0; i < 2; ++i) {
            int m = m0i + i * 64;
            if (K2 == 0 || kb < K1)
                ra[i] = *(const float4*)(A1 + (r0 + m) * K1 + kb + kq);
            else
                ra[i] = *(const float4*)(A2 + (r0 + m) * K2 + (kb - K1) + kq);
        }
        rbv = *(const float4*)(W + (size_t)(n0 + m0i) * KT + kb + kq);
    };

    auto sts_stage = [&](int buf) {
        uint32_t* Ab = As + buf * (16 * 136);
        uint32_t* Bb = Bs + buf * (16 * 72);
        #pragma unroll
        for (int i = 0; i < 2; ++i) {
            int m = m0i + i * 64;
            float va[4] = {ra[i].x, ra[i].y, ra[i].z, ra[i].w};
            #pragma unroll
            for (int j = 0; j < 4; ++j) {
                int k = kq + j;
                int sw = ((k >> 2) & 3) << 3;
                Ab[k * 136 + (m ^ sw)] = f2tf(va[j]);
            }
        }
        float vb[4] = {rbv.x, rbv.y, rbv.z, rbv.w};
        #pragma unroll
        for (int j = 0; j < 4; ++j) {
            int k = kq + j;
            int sw = ((k >> 2) & 3) << 3;
            Bb[k * 72 + (m0i ^ sw)] = f2tf(vb[j]);
        }
    };

    auto compute_stage = [&](int buf) {
        const uint32_t* Ab = As + buf * (16 * 136);
        const uint32_t* Bb = Bs + buf * (16 * 72);
        #pragma unroll
        for (int k8 = 0; k8 < 2; ++k8) {
            const int kk = k8 * 8;
            const int s0 = ((2 * k8) & 3) << 3;
            const int s1 = ((2 * k8 + 1) & 3) << 3;
            uint32_t a[2][4];
            #pragma unroll
            for (int mt = 0; mt < 2; ++mt) {
                int m0 = wm + mt * 16;
                a[mt][0] = Ab[(kk + tg) * 136 + ((m0 + g) ^ s0)];
                a[mt][1] = Ab[(kk + tg) * 136 + ((m0 + g + 8) ^ s0)];
                a[mt][2] = Ab[(kk + tg + 4) * 136 + ((m0 + g) ^ s1)];
                a[mt][3] = Ab[(kk + tg + 4) * 136 + ((m0 + g + 8) ^ s1)];
            }
            uint32_t bf[4][2];
            #pragma unroll
            for (int nt = 0; nt < 4; ++nt) {
                int q0 = wn + nt * 8 + g;
                bf[nt][0] = Bb[(kk + tg) * 72 + (q0 ^ s0)];
                bf[nt][1] = Bb[(kk + tg + 4) * 72 + (q0 ^ s1)];
            }
            #pragma unroll
            for (int mt = 0; mt < 2; ++mt)
                #pragma unroll
                for (int nt = 0; nt < 4; ++nt)
                    MMA_TF32(acc[mt][nt], a[mt], bf[nt]);
        }
    };

    ldg_stage(0);
    sts_stage(0);
    __syncthreads();
    int buf = 0;
    #pragma unroll 1
    for (int s = 0; s < NS; ++s) {
        if (s < NS - 1) ldg_stage(s + 1);
        compute_stage(buf);
        if (s < NS - 1) {
            sts_stage(buf ^ 1);
            __syncthreads();
            buf ^= 1;
        }
    }

    // epilogue: direct STG.64 (2 adjacent cols per acc pair)
    #pragma unroll
    for (int mt = 0; mt < 2; ++mt) {
        #pragma unroll
        for (int nt = 0; nt < 4; ++nt) {
            size_t r = r0 + wm + mt * 16 + g;
            int    c = n0 + wn + nt * 8 + tg * 2;
            float v0 = acc[mt][nt][0], v1 = acc[mt][nt][1];
            float v2 = acc[mt][nt][2], v3 = acc[mt][nt][3];
            if (EPI >= 1) {
                float b0 = bias[c], b1 = bias[c + 1];
                v0 += b0; v1 += b1; v2 += b0; v3 += b1;
            }
            if (EPI == 2) {
                v0 = fmaxf(v0, 0.f); v1 = fmaxf(v1, 0.f);
                v2 = fmaxf(v2, 0.f); v3 = fmaxf(v3, 0.f);
            }
            *(float2*)(C + r * ldc + c)       = make_float2(v0, v1);
            *(float2*)(C + (r + 8) * ldc + c) = make_float2(v2, v3);
        }
    }
}

// ---------------------------------------------------------------------------
// kB: per-batch masked attention.  one CTA (128 thr) per batch b.
//   reads H[b] [32,256]; computes s_src/s_dst, masked softmax, agg = alpha@H.
// ---------------------------------------------------------------------------
// dynamic smem (floats): Hs[32][257] | alpha[4][32][33] | ssrc[128] | sdst[128]
//                        | sas[256] | sad[256] | msk[32*33] (int)
#define KB_HS    0
#define KB_ALPHA 8224
#define KB_SSRC  (KB_ALPHA + 4*32*33)    // 12448
#define KB_SDST  (KB_SSRC + 128)
#define KB_SAS   (KB_SDST + 128)
#define KB_SAD   (KB_SAS + 256)
#define KB_MSK   (KB_SAD + 256)          // int region
#define KB_SMEM  ((KB_MSK + 32*33) * 4)  // 57088 B

__global__ void __launch_bounds__(128) kB_attn(
    const float* __restrict__ H, const int* __restrict__ mask,
    const float* __restrict__ asrc, const float* __restrict__ adst,
    float* __restrict__ agg)
{
    extern __shared__ float smf[];
    float* Hs    = smf + KB_HS;      // pitch 257
    float* alpha = smf + KB_ALPHA;   // [4][32][33]
    float* ssrc  = smf + KB_SSRC;
    float* sdst  = smf + KB_SDST;
    float* sas   = smf + KB_SAS;
    float* sad   = smf + KB_SAD;
    int*   msk   = (int*)(smf + KB_MSK); // pitch 33

    const int tid  = threadIdx.x;
    const int lane = tid & 31;
    const int warp = tid >> 5;
    const int b    = blockIdx.x;

    // load H[b] into Hs (pitch 257) — scalar stores (pitch 257 is not
    // 16B-aligned per row; float4 smem stores here would trap)
    const float* Hb = H + (size_t)b * (32 * 256);
    for (int i = tid; i < 32 * 256; i += 128) {
        int a = i >> 8, c = i & 255;
        Hs[a * 257 + c] = Hb[i];
    }
    for (int i = tid; i < 256; i += 128) { sas[i] = asrc[i]; sad[i] = adst[i]; }
    for (int i = tid; i < 32 * 32; i += 128) {
        int r = i >> 5, c = i & 31;
        msk[r * 33 + c] = mask[(size_t)b * (32 * 32) + i];
    }
    __syncthreads();

    // s_src / s_dst: warp = head, lane = agent row
    {
        int hd = warp;
        float vs = 0.f, vd = 0.f;
        const float* hr = Hs + lane * 257 + hd * 64;
        #pragma unroll
        for (int d = 0; d < 64; ++d) {
            float h = hr[d];
            vs = fmaf(h, sas[hd * 64 + d], vs);
            vd = fmaf(h, sad[hd * 64 + d], vd);
        }
        ssrc[hd * 32 + lane] = vs;
        sdst[hd * 32 + lane] = vd;
    }
    __syncthreads();

    // masked softmax: thread = (hd, i)
    {
        int hd = tid >> 5, i = tid & 31;
        float si = ssrc[hd * 32 + i];
        float v[32];
        float m = -3.4e38f;
        #pragma unroll
        for (int j = 0; j < 32; ++j) {
            float e_ = si + sdst[hd * 32 + j];
            float l  = e_ > 0.f ? e_ : 0.2f * e_;
            if (msk[i * 33 + j] <= 0) l = -1e9f;
            v[j] = l; m = fmaxf(m, l);
        }
        float s = 0.f;
        #pragma unroll
        for (int j = 0; j < 32; ++j) { v[j] = __expf(v[j] - m); s += v[j]; }
        float inv = 1.f / s;
        #pragma unroll
        for (int j = 0; j < 32; ++j) alpha[(hd * 32 + i) * 33 + j] = v[j] * inv;
    }
    __syncthreads();

    // agg: thread owns cols c = tid and c+128; Hs columns cached in regs
    {
        float v0[32], v1[32];
        #pragma unroll
        for (int j = 0; j < 32; ++j) {
            v0[j] = Hs[j * 257 + tid];
            v1[j] = Hs[j * 257 + tid + 128];
        }
        const int hd0 = tid >> 6;       // 0 or 1 (warp-uniform)
        const int hd1 = hd0 + 2;
        float* aggb = agg + (size_t)b * (32 * 256);
        #pragma unroll 4
        for (int a = 0; a < 32; ++a) {
            const float* al0 = alpha + (hd0 * 32 + a) * 33;
            const float* al1 = alpha + (hd1 * 32 + a) * 33;
            float s0 = 0.f, s1 = 0.f;
            #pragma unroll
            for (int j = 0; j < 32; ++j) {
                s0 = fmaf(al0[j], v0[j], s0);
                s1 = fmaf(al1[j], v1[j], s1);
            }
            aggb[a * 256 + tid]       = s0;
            aggb[a * 256 + tid + 128] = s1;
        }
    }
}

// ---------------------------------------------------------------------------
// k2: GRU via tf32 MMA (unchanged from R2 — proven)
// ---------------------------------------------------------------------------
#define K2_SMEM 68096

__global__ void __launch_bounds__(256, 2) k2_gru_tc(
    const float* __restrict__ xr,  const float* __restrict__ hin,
    const float* __restrict__ Wih, const float* __restrict__ Whh,
    const float* __restrict__ bih, const float* __restrict__ bhh,
    float* __restrict__ hh_out)
{
    extern __shared__ uint32_t sm2[];
    uint32_t* As = sm2;
    uint32_t* Bs = sm2 + 2 * 16 * 136;

    const int tid  = threadIdx.x;
    const int lane = tid & 31;
    const int warp = tid >> 5;
    const int wm = (warp & 3) * 32;
    const int wn = (warp >> 2) * 64;
    const int g  = lane >> 2;
    const int tg = lane & 3;
    const size_t r0 = (size_t)blockIdx.y * 128;
    const int c0 = blockIdx.x * 32;

    const int m0i = tid >> 2;
    const int kqA = (tid & 3) * 4;

    float4 ra[2], rb[2];

    float acc[2][8][4];
    #pragma unroll
    for (int mt = 0; mt < 2; ++mt)
        #pragma unroll
        for (int nt = 0; nt < 8; ++nt)
            #pragma unroll
            for (int e = 0; e < 4; ++e) acc[mt][nt][e] = 0.f;

    auto ldg_stage = [&](int s) {
        const int kb = s * 16;
        const int kbl = kb & 255;
        const float* srcA = (kb < 256) ? xr : hin;
        const float* srcW = (kb < 256) ? Wih : Whh;
        #pragma unroll
        for (int i = 0; i < 2; ++i) {
            int m = m0i + i * 64;
            ra[i] = *(const float4*)(srcA + (r0 + m) * 256 + kbl + kqA);
            int grp = m >> 5, cl = c0 + (m & 31);
            bool zero = (kb < 256) ? (grp == 3) : (grp == 2);
            int wrow = (grp == 0) ? cl : (grp == 1) ? 256 + cl : 512 + cl;
            if (zero) rb[i] = make_float4(0.f, 0.f, 0.f, 0.f);
            else      rb[i] = *(const float4*)(srcW + (size_t)wrow * 256 + kbl + kqA);
        }
    };

    auto sts_stage = [&](int buf) {
        uint32_t* Ab = As + buf * (16 * 136);
        uint32_t* Bb = Bs + buf * (16 * 136);
        #pragma unroll
        for (int i = 0; i < 2; ++i) {
            int m = m0i + i * 64;
            float va[4] = {ra[i].x, ra[i].y, ra[i].z, ra[i].w};
            float vb[4] = {rb[i].x, rb[i].y, rb[i].z, rb[i].w};
            #pragma unroll
            for (int j = 0; j < 4; ++j) {
                int k  = kqA + j;
                int sw = ((k >> 2) & 3) << 3;
                Ab[k * 136 + (m ^ sw)] = f2tf(va[j]);
                Bb[k * 136 + (m ^ sw)] = f2tf(vb[j]);
            }
        }
    };

    auto compute_stage = [&](int buf) {
        const uint32_t* Ab = As + buf * (16 * 136);
        const uint32_t* Bb = Bs + buf * (16 * 136);
        #pragma unroll
        for (int k8 = 0; k8 < 2; ++k8) {
            const int kk = k8 * 8;
            const int s0 = ((2 * k8) & 3) << 3;
            const int s1 = ((2 * k8 + 1) & 3) << 3;
            uint32_t a[2][4];
            #pragma unroll
            for (int mt = 0; mt < 2; ++mt) {
                int m0 = wm + mt * 16;
                a[mt][0] = Ab[(kk + tg) * 136 + ((m0 + g) ^ s0)];
                a[mt][1] = Ab[(kk + tg) * 136 + ((m0 + g + 8) ^ s0)];
                a[mt][2] = Ab[(kk + tg + 4) * 136 + ((m0 + g) ^ s1)];
                a[mt][3] = Ab[(kk + tg + 4) * 136 + ((m0 + g + 8) ^ s1)];
            }
            uint32_t bf[8][2];
            #pragma unroll
            for (int nt = 0; nt < 8; ++nt) {
                int q0 = wn + nt * 8 + g;
                bf[nt][0] = Bb[(kk + tg) * 136 + (q0 ^ s0)];
                bf[nt][1] = Bb[(kk + tg + 4) * 136 + (q0 ^ s1)];
            }
            #pragma unroll
            for (int mt = 0; mt < 2; ++mt)
                #pragma unroll
                for (int nt = 0; nt < 8; ++nt)
                    MMA_TF32(acc[mt][nt], a[mt], bf[nt]);
        }
    };

    ldg_stage(0);
    sts_stage(0);
    __syncthreads();
    int buf = 0;
    for (int s = 0; s < 32; ++s) {
        if (s < 31) ldg_stage(s + 1);
        compute_stage(buf);
        if (s < 31) {
            sts_stage(buf ^ 1);
            __syncthreads();
            buf ^= 1;
        }
    }
    __syncthreads();

    float* Sacc = (float*)sm2;
    #pragma unroll
    for (int mt = 0; mt < 2; ++mt) {
        #pragma unroll
        for (int nt = 0; nt < 8; ++nt) {
            int rl = wm + mt * 16 + g;
            int q  = wn + nt * 8 + tg * 2;
            Sacc[q * 133 + rl]           = acc[mt][nt][0];
            Sacc[(q + 1) * 133 + rl]     = acc[mt][nt][1];
            Sacc[q * 133 + rl + 8]       = acc[mt][nt][2];
            Sacc[(q + 1) * 133 + rl + 8] = acc[mt][nt][3];
        }
    }
    __syncthreads();

    const int col = tid & 31;
    const int c   = c0 + col;
    const int rg0 = (tid >> 5) * 16;
    const float br  = bih[c] + bhh[c];
    const float bz  = bih[256 + c] + bhh[256 + c];
    const float bni = bih[512 + c];
    const float bnh = bhh[512 + c];
    #pragma unroll
    for (int j = 0; j < 16; ++j) {
        int rl = rg0 + j;
        float gr  = Sacc[col * 133 + rl];
        float gz  = Sacc[(32 + col) * 133 + rl];
        float gni = Sacc[(64 + col) * 133 + rl];
        float gnh = Sacc[(96 + col) * 133 + rl];
        float hprev = hin[(r0 + rl) * 256 + c];
        float rg_ = sigf(gr + br);
        float zg_ = sigf(gz + bz);
        float ng_ = tanhf(gni + bni + rg_ * (gnh + bnh));
        hh_out[(r0 + rl) * 256 + c] = (1.f - zg_) * ng_ + zg_ * hprev;
    }
}

// ---------------------------------------------------------------------------
// k3: LayerNorm + fc2 (one warp per row) — unchanged
// ---------------------------------------------------------------------------
__global__ void __launch_bounds__(256) k3_ln_fc2(
    const float* __restrict__ hh, const float* __restrict__ lng,
    const float* __restrict__ lnb, const float* __restrict__ W2,
    const float* __restrict__ b2, float* __restrict__ q, int nrows)
{
    int warp = (blockIdx.x * blockDim.x + threadIdx.x) >> 5;
    int lane = threadIdx.x & 31;
    if (warp >= nrows) return;
    const float* hr = hh + (size_t)warp * RDIM;

    float v[8];
    float s = 0.f;
    #pragma unroll
    for (int i = 0; i < 8; ++i) { v[i] = hr[lane + 32 * i]; s += v[i]; }
    #pragma unroll
    for (int o = 16; o; o >>= 1) s += __shfl_xor_sync(0xffffffffu, s, o);
    float mu = s * (1.f / 256.f);
    float vs = 0.f;
    #pragma unroll
    for (int i = 0; i < 8; ++i) { float d = v[i] - mu; vs += d * d; }
    #pragma unroll
    for (int o = 16; o; o >>= 1) vs += __shfl_xor_sync(0xffffffffu, vs, o);
    float inv = rsqrtf(vs * (1.f / 256.f) + 1e-5f);

    float hn[8];
    #pragma unroll
    for (int i = 0; i < 8; ++i)
        hn[i] = (v[i] - mu) * inv * lng[lane + 32 * i] + lnb[lane + 32 * i];

    #pragma unroll
    for (int j = 0; j < NACT; ++j) {
        float p = 0.f;
        #pragma unroll
        for (int i = 0; i < 8; ++i) p = fmaf(hn[i], W2[j * RDIM + lane + 32 * i], p);
        #pragma unroll
        for (int o = 16; o; o >>= 1) p += __shfl_xor_sync(0xffffffffu, p, o);
        if (lane == j) q[(size_t)warp * NACT + j] = p + b2[j];
    }
}

// ---------------------------------------------------------------------------
extern "C" void kernel_launch(void* const* d_in, const int* in_sizes, int n_in,
                              void* d_out, int out_size)
{
    const float* inputs = (const float*)d_in[0];
    const float* hidden = (const float*)d_in[1];
    const int*   mask   = (const int*)  d_in[2];
    const float* Wfc    = (const float*)d_in[3];
    const float* bfc    = (const float*)d_in[4];
    const float* Wh     = (const float*)d_in[5];
    const float* asrc   = (const float*)d_in[6];
    const float* adst   = (const float*)d_in[7];
    const float* Wo     = (const float*)d_in[8];
    const float* bo     = (const float*)d_in[9];
    const float* W1     = (const float*)d_in[10];
    const float* b1     = (const float*)d_in[11];
    const float* Wih    = (const float*)d_in[12];
    const float* Whh    = (const float*)d_in[13];
    const float* bih    = (const float*)d_in[14];
    const float* bhh    = (const float*)d_in[15];
    const float* lng    = (const float*)d_in[16];
    const float* lnb    = (const float*)d_in[17];
    const float* W2     = (const float*)d_in[18];
    const float* b2     = (const float*)d_in[19];

    const int B = in_sizes[0] / (AN * OBS);       // 4096
    const int nrows = B * AN;                     // 131072
    const int mblk = nrows / 128;                 // 1024

    float* q_out  = (float*)d_out;
    float* hh_out = (float*)d_out + (size_t)nrows * NACT;

    float *xe, *bh, *bg, *wht, *wot;
    cudaGetSymbolAddress((void**)&xe,  g_buf64);
    cudaGetSymbolAddress((void**)&bh,  g_bufH);
    cudaGetSymbolAddress((void**)&bg,  g_bufG);
    cudaGetSymbolAddress((void**)&wht, g_WhT);
    cudaGetSymbolAddress((void**)&wot, g_WoT);

    cudaFuncSetAttribute(kB_attn,   cudaFuncAttributeMaxDynamicSharedMemorySize, KB_SMEM);
    cudaFuncSetAttribute(k2_gru_tc, cudaFuncAttributeMaxDynamicSharedMemorySize, K2_SMEM);

    k0_prep<<<64, 256>>>(Wh, Wo, wht, wot);

    // G1: XE = inputs @ Wfc^T + bfc          [M,64]
    gemm_tn<128, 0, 1><<<dim3(1, mblk), 256, GEMM_SMEM>>>(inputs, nullptr, Wfc, bfc, xe);
    // G2: H = XE @ WhT^T                     [M,256]
    gemm_tn<64, 0, 0><<<dim3(4, mblk), 256, GEMM_SMEM>>>(xe, nullptr, wht, nullptr, bh);
    // attention: agg = softmax(mask, leaky(s_i+s_j)) @ H
    kB_attn<<<B, 128, KB_SMEM>>>(bh, mask, asrc, adst, bg);
    // G3: ATT = agg @ WoT^T + bo             [M,64] (overwrites XE)
    gemm_tn<256, 0, 1><<<dim3(1, mblk), 256, GEMM_SMEM>>>(bg, nullptr, wot, bo, xe);
    // G4: XR = relu([inputs|ATT] @ W1^T+b1)  [M,256] (overwrites agg)
    gemm_tn<128, 64, 2><<<dim3(4, mblk), 256, GEMM_SMEM>>>(inputs, xe, W1, b1, bg);
    // GRU
    k2_gru_tc<<<dim3(8, mblk), 256, K2_SMEM>>>(bg, hidden, Wih, Whh, bih, bhh, hh_out);
    // LN + fc2
    k3_ln_fc2<<<(nrows + 7) / 8, 256>>>(hh_out, lng, lnb, W2, b2, q_out, nrows);
}

// round 6
// speedup vs baseline: 4.6053x; 1.3358x over previous
#include <cuda_runtime.h>
#include <cuda_bf16.h>
#include <stdint.h>

// Problem constants
#define AN   32      // agents
#define OBS  128
#define EDIM 64
#define DDIM 64
#define HHEADS 4
#define RDIM 256
#define NACT 16
#define ZDIM 192     // OBS + EDIM
#define MAXROWS (4096*32)

// Scratch buffers (aliased across pipeline stages)
__device__ float g_buf64[MAXROWS * 64];    // XE -> ATT
__device__ float g_bufH [MAXROWS * RDIM];  // H
__device__ float g_bufG [MAXROWS * RDIM];  // agg -> XR
__device__ float g_WhT  [256 * 64];
__device__ float g_WoT  [64 * 256];

__device__ __forceinline__ float sigf(float x) { return 1.0f / (1.0f + __expf(-x)); }

__device__ __forceinline__ uint32_t f2tf(float x) {
    uint32_t r;
    asm("cvt.rna.tf32.f32 %0, %1;" : "=r"(r) : "f"(x));
    return r;
}

#define MMA_TF32(d, a, b)                                                     \
    asm volatile(                                                             \
        "mma.sync.aligned.m16n8k8.row.col.f32.tf32.tf32.f32 "                 \
        "{%0,%1,%2,%3},{%4,%5,%6,%7},{%8,%9},{%0,%1,%2,%3};"                  \
        : "+f"(d[0]), "+f"(d[1]), "+f"(d[2]), "+f"(d[3])                      \
        : "r"(a[0]), "r"(a[1]), "r"(a[2]), "r"(a[3]), "r"(b[0]), "r"(b[1]))

__device__ __forceinline__ void cpa16(uint32_t dst, const float* src) {
    asm volatile("cp.async.cg.shared.global [%0], [%1], 16;"
                 :: "r"(dst), "l"(src));
}
#define CPA_COMMIT()  asm volatile("cp.async.commit_group;" ::: "memory")
#define CPA_WAIT(N)   asm volatile("cp.async.wait_group %0;" :: "n"(N) : "memory")

// ---------------------------------------------------------------------------
// k0: tiny transposes  WhT[h*64+d][e] = W_h[h][e][d];  WoT[e][k] = W_o[k][e]
// ---------------------------------------------------------------------------
__global__ void k0_prep(const float* __restrict__ Wh, const float* __restrict__ Wo,
                        float* __restrict__ WhT, float* __restrict__ WoT)
{
    int tid = blockIdx.x * blockDim.x + threadIdx.x;
    int stride = gridDim.x * blockDim.x;
    for (int i = tid; i < 256 * 64; i += stride) {
        int n = i >> 6, e = i & 63;
        int h = n >> 6, d = n & 63;
        WhT[i] = Wh[(h * 64 + e) * 64 + d];
    }
    for (int i = tid; i < 64 * 256; i += stride) {
        int e = i >> 8, k = i & 255;
        WoT[i] = Wo[k * 64 + e];
    }
}

// ---------------------------------------------------------------------------
// Generic tf32 GEMM:  C[M, N] = EPI( [A1|A2] @ W^T + bias )   (proven R4)
// ---------------------------------------------------------------------------
#define GEMM_SMEM ((2*16*136 + 2*16*72) * 4)

template<int K1, int K2, int EPI>
__global__ void __launch_bounds__(256) gemm_tn(
    const float* __restrict__ A1, const float* __restrict__ A2,
    const float* __restrict__ W,  const float* __restrict__ bias,
    float* __restrict__ C)
{
    constexpr int KT = K1 + K2;
    constexpr int NS = KT / 16;
    extern __shared__ uint32_t sg[];
    uint32_t* As = sg;                   // [2][16][136]
    uint32_t* Bs = sg + 2 * 16 * 136;    // [2][16][72]

    const int tid  = threadIdx.x;
    const int lane = tid & 31;
    const int warp = tid >> 5;
    const int wm = (warp & 3) * 32;
    const int wn = (warp >> 2) * 32;
    const int g  = lane >> 2;
    const int tg = lane & 3;
    const size_t r0 = (size_t)blockIdx.y * 128;
    const int n0 = blockIdx.x * 64;
    const int ldc = gridDim.x * 64;

    const int m0i = tid >> 2;           // 0..63
    const int kq  = (tid & 3) * 4;

    float4 ra[2], rbv;

    float acc[2][4][4];
    #pragma unroll
    for (int mt = 0; mt < 2; ++mt)
        #pragma unroll
        for (int nt = 0; nt < 4; ++nt)
            #pragma unroll
            for (int e = 0; e < 4; ++e) acc[mt][nt][e] = 0.f;

    auto ldg_stage = [&](int s) {
        const int kb = s * 16;
        #pragma unroll
        for (int i = 0; i < 2; ++i) {
            int m = m0i + i * 64;
            if (K2 == 0 || kb < K1)
                ra[i] = *(const float4*)(A1 + (r0 + m) * K1 + kb + kq);
            else
                ra[i] = *(const float4*)(A2 + (r0 + m) * K2 + (kb - K1) + kq);
        }
        rbv = *(const float4*)(W + (size_t)(n0 + m0i) * KT + kb + kq);
    };

    auto sts_stage = [&](int buf) {
        uint32_t* Ab = As + buf * (16 * 136);
        uint32_t* Bb = Bs + buf * (16 * 72);
        #pragma unroll
        for (int i = 0; i < 2; ++i) {
            int m = m0i + i * 64;
            float va[4] = {ra[i].x, ra[i].y, ra[i].z, ra[i].w};
            #pragma unroll
            for (int j = 0; j < 4; ++j) {
                int k = kq + j;
                int sw = ((k >> 2) & 3) << 3;
                Ab[k * 136 + (m ^ sw)] = f2tf(va[j]);
            }
        }
        float vb[4] = {rbv.x, rbv.y, rbv.z, rbv.w};
        #pragma unroll
        for (int j = 0; j < 4; ++j) {
            int k = kq + j;
            int sw = ((k >> 2) & 3) << 3;
            Bb[k * 72 + (m0i ^ sw)] = f2tf(vb[j]);
        }
    };

    auto compute_stage = [&](int buf) {
        const uint32_t* Ab = As + buf * (16 * 136);
        const uint32_t* Bb = Bs + buf * (16 * 72);
        #pragma unroll
        for (int k8 = 0; k8 < 2; ++k8) {
            const int kk = k8 * 8;
            const int s0 = ((2 * k8) & 3) << 3;
            const int s1 = ((2 * k8 + 1) & 3) << 3;
            uint32_t a[2][4];
            #pragma unroll
            for (int mt = 0; mt < 2; ++mt) {
                int m0 = wm + mt * 16;
                a[mt][0] = Ab[(kk + tg) * 136 + ((m0 + g) ^ s0)];
                a[mt][1] = Ab[(kk + tg) * 136 + ((m0 + g + 8) ^ s0)];
                a[mt][2] = Ab[(kk + tg + 4) * 136 + ((m0 + g) ^ s1)];
                a[mt][3] = Ab[(kk + tg + 4) * 136 + ((m0 + g + 8) ^ s1)];
            }
            uint32_t bf[4][2];
            #pragma unroll
            for (int nt = 0; nt < 4; ++nt) {
                int q0 = wn + nt * 8 + g;
                bf[nt][0] = Bb[(kk + tg) * 72 + (q0 ^ s0)];
                bf[nt][1] = Bb[(kk + tg + 4) * 72 + (q0 ^ s1)];
            }
            #pragma unroll
            for (int mt = 0; mt < 2; ++mt)
                #pragma unroll
                for (int nt = 0; nt < 4; ++nt)
                    MMA_TF32(acc[mt][nt], a[mt], bf[nt]);
        }
    };

    ldg_stage(0);
    sts_stage(0);
    __syncthreads();
    int buf = 0;
    #pragma unroll 1
    for (int s = 0; s < NS; ++s) {
        if (s < NS - 1) ldg_stage(s + 1);
        compute_stage(buf);
        if (s < NS - 1) {
            sts_stage(buf ^ 1);
            __syncthreads();
            buf ^= 1;
        }
    }

    #pragma unroll
    for (int mt = 0; mt < 2; ++mt) {
        #pragma unroll
        for (int nt = 0; nt < 4; ++nt) {
            size_t r = r0 + wm + mt * 16 + g;
            int    c = n0 + wn + nt * 8 + tg * 2;
            float v0 = acc[mt][nt][0], v1 = acc[mt][nt][1];
            float v2 = acc[mt][nt][2], v3 = acc[mt][nt][3];
            if (EPI >= 1) {
                float b0 = bias[c], b1 = bias[c + 1];
                v0 += b0; v1 += b1; v2 += b0; v3 += b1;
            }
            if (EPI == 2) {
                v0 = fmaxf(v0, 0.f); v1 = fmaxf(v1, 0.f);
                v2 = fmaxf(v2, 0.f); v3 = fmaxf(v3, 0.f);
            }
            *(float2*)(C + r * ldc + c)       = make_float2(v0, v1);
            *(float2*)(C + (r + 8) * ldc + c) = make_float2(v2, v3);
        }
    }
}

// ---------------------------------------------------------------------------
// kB: per-batch masked attention (unchanged, proven)
// ---------------------------------------------------------------------------
#define KB_HS    0
#define KB_ALPHA 8224
#define KB_SSRC  (KB_ALPHA + 4*32*33)    // 12448
#define KB_SDST  (KB_SSRC + 128)
#define KB_SAS   (KB_SDST + 128)
#define KB_SAD   (KB_SAS + 256)
#define KB_MSK   (KB_SAD + 256)          // int region
#define KB_SMEM  ((KB_MSK + 32*33) * 4)  // 57088 B

__global__ void __launch_bounds__(128) kB_attn(
    const float* __restrict__ H, const int* __restrict__ mask,
    const float* __restrict__ asrc, const float* __restrict__ adst,
    float* __restrict__ agg)
{
    extern __shared__ float smf[];
    float* Hs    = smf + KB_HS;      // pitch 257
    float* alpha = smf + KB_ALPHA;   // [4][32][33]
    float* ssrc  = smf + KB_SSRC;
    float* sdst  = smf + KB_SDST;
    float* sas   = smf + KB_SAS;
    float* sad   = smf + KB_SAD;
    int*   msk   = (int*)(smf + KB_MSK); // pitch 33

    const int tid  = threadIdx.x;
    const int lane = tid & 31;
    const int warp = tid >> 5;
    const int b    = blockIdx.x;

    const float* Hb = H + (size_t)b * (32 * 256);
    for (int i = tid; i < 32 * 256; i += 128) {
        int a = i >> 8, c = i & 255;
        Hs[a * 257 + c] = Hb[i];
    }
    for (int i = tid; i < 256; i += 128) { sas[i] = asrc[i]; sad[i] = adst[i]; }
    for (int i = tid; i < 32 * 32; i += 128) {
        int r = i >> 5, c = i & 31;
        msk[r * 33 + c] = mask[(size_t)b * (32 * 32) + i];
    }
    __syncthreads();

    {
        int hd = warp;
        float vs = 0.f, vd = 0.f;
        const float* hr = Hs + lane * 257 + hd * 64;
        #pragma unroll
        for (int d = 0; d < 64; ++d) {
            float h = hr[d];
            vs = fmaf(h, sas[hd * 64 + d], vs);
            vd = fmaf(h, sad[hd * 64 + d], vd);
        }
        ssrc[hd * 32 + lane] = vs;
        sdst[hd * 32 + lane] = vd;
    }
    __syncthreads();

    {
        int hd = tid >> 5, i = tid & 31;
        float si = ssrc[hd * 32 + i];
        float v[32];
        float m = -3.4e38f;
        #pragma unroll
        for (int j = 0; j < 32; ++j) {
            float e_ = si + sdst[hd * 32 + j];
            float l  = e_ > 0.f ? e_ : 0.2f * e_;
            if (msk[i * 33 + j] <= 0) l = -1e9f;
            v[j] = l; m = fmaxf(m, l);
        }
        float s = 0.f;
        #pragma unroll
        for (int j = 0; j < 32; ++j) { v[j] = __expf(v[j] - m); s += v[j]; }
        float inv = 1.f / s;
        #pragma unroll
        for (int j = 0; j < 32; ++j) alpha[(hd * 32 + i) * 33 + j] = v[j] * inv;
    }
    __syncthreads();

    {
        float v0[32], v1[32];
        #pragma unroll
        for (int j = 0; j < 32; ++j) {
            v0[j] = Hs[j * 257 + tid];
            v1[j] = Hs[j * 257 + tid + 128];
        }
        const int hd0 = tid >> 6;
        const int hd1 = hd0 + 2;
        float* aggb = agg + (size_t)b * (32 * 256);
        #pragma unroll 4
        for (int a = 0; a < 32; ++a) {
            const float* al0 = alpha + (hd0 * 32 + a) * 33;
            const float* al1 = alpha + (hd1 * 32 + a) * 33;
            float s0 = 0.f, s1 = 0.f;
            #pragma unroll
            for (int j = 0; j < 32; ++j) {
                s0 = fmaf(al0[j], v0[j], s0);
                s1 = fmaf(al1[j], v1[j], s1);
            }
            aggb[a * 256 + tid]       = s0;
            aggb[a * 256 + tid + 128] = s1;
        }
    }
}

// ---------------------------------------------------------------------------
// k2: GRU via tf32 MMA, cp.async 3-stage pipeline, dual-phase accumulators.
//
// Per CTA: 128 rows x 32 output cols. MMA n-space = 96:
//   npos  0-31: r-gate cols 0-31     (accumulated over BOTH phases)
//   npos 32-47: n-gate cols 0-15     (phase-split: acc_i / acc_h)
//   npos 48-79: z-gate cols 0-31     (both phases)
//   npos 80-95: n-gate cols 16-31    (phase-split)
// Phase 0: A = xr,  B = Wih, K=256.  Phase 1: A = h_in, B = Whh, K=256.
// Raw fp32 bits fed to tf32 MMA (HW truncation; no cvt, no register staging).
// smem stage: A[128][20] + B[96][20] floats, 3 buffers. Epilogue via Sacc
// q-space 128 = {r, z, n_i, n_h} (identical to proven R4 epilogue).
// ---------------------------------------------------------------------------
#define K2_STAGEF 4480                   // floats per stage buffer (2560 A + 1920 B)
#define K2_SMEM   68096                  // max(3*4480*4 = 53760, 128*133*4 = 68096)

__global__ void __launch_bounds__(256, 2) k2_gru_tc(
    const float* __restrict__ xr,  const float* __restrict__ hin,
    const float* __restrict__ Wih, const float* __restrict__ Whh,
    const float* __restrict__ bih, const float* __restrict__ bhh,
    float* __restrict__ hh_out)
{
    extern __shared__ float smf[];
    const uint32_t sbase = (uint32_t)__cvta_generic_to_shared(smf);

    const int tid  = threadIdx.x;
    const int lane = tid & 31;
    const int warp = tid >> 5;
    const int wm  = (warp & 3) * 32;     // row group
    const int wn  = (warp >> 2) * 48;    // n group (0 or 48)
    const int g   = lane >> 2;
    const int tg  = lane & 3;
    const size_t r0 = (size_t)blockIdx.y * 128;
    const int c0 = blockIdx.x * 32;

    // ---- staging assignments (fixed per thread) ----
    // A: 512 chunks of 16B: idx -> m = idx>>2, k4 = (idx&3)*4
    const int mA  = tid >> 2;            // 0..63 (second chunk: +64)
    const int k4A = (tid & 3) * 4;
    const size_t aoff0 = (r0 + mA) * 256 + k4A;
    const size_t aoff1 = (r0 + mA + 64) * 256 + k4A;
    const uint32_t adst0 = (uint32_t)(mA * 20 + k4A);
    const uint32_t adst1 = (uint32_t)((mA + 64) * 20 + k4A);
    // B: 384 chunks: idx -> n = idx>>2, k4 = (idx&3)*4 (threads <128 do 2nd)
    auto wrow_of = [&](int n) {
        return (n < 32) ? (c0 + n)
             : (n < 48) ? (512 + c0 + (n - 32))
             : (n < 80) ? (256 + c0 + (n - 48))
                        : (528 + c0 + (n - 80));
    };
    const int nB0 = tid >> 2;            // 0..63
    const int k4B = (tid & 3) * 4;
    const size_t boff0 = (size_t)wrow_of(nB0) * 256 + k4B;
    const size_t boff1 = (size_t)wrow_of(nB0 + 64) * 256 + k4B;
    const uint32_t bdst0 = (uint32_t)(2560 + nB0 * 20 + k4B);
    const uint32_t bdst1 = (uint32_t)(2560 + (nB0 + 64) * 20 + k4B);

    auto issue = [&](int s) {
        const int buf = s % 3;
        const int kloc = (s & 15) * 16;
        const float* Asrc = (s < 16) ? xr  : hin;
        const float* Wsrc = (s < 16) ? Wih : Whh;
        const uint32_t sb = sbase + (uint32_t)(buf * K2_STAGEF * 4);
        cpa16(sb + adst0 * 4, Asrc + aoff0 + kloc);
        cpa16(sb + adst1 * 4, Asrc + aoff1 + kloc);
        cpa16(sb + bdst0 * 4, Wsrc + boff0 + kloc);
        if (tid < 128) cpa16(sb + bdst1 * 4, Wsrc + boff1 + kloc);
        CPA_COMMIT();
    };

    // ---- accumulators ----
    float acc [2][4][4];       // shared tiles (r, z): [mt][nt][frag]
    float accd[2][2][2][4];    // dual tiles (n): [phase][mt][j][frag]
    #pragma unroll
    for (int mt = 0; mt < 2; ++mt) {
        #pragma unroll
        for (int nt = 0; nt < 4; ++nt)
            #pragma unroll
            for (int e = 0; e < 4; ++e) acc[mt][nt][e] = 0.f;
        #pragma unroll
        for (int p = 0; p < 2; ++p)
            #pragma unroll
            for (int j = 0; j < 2; ++j)
                #pragma unroll
                for (int e = 0; e < 4; ++e) accd[p][mt][j][e] = 0.f;
    }

    auto compute = [&](int buf, int ph) {
        const float* Ab = smf + buf * K2_STAGEF;
        const float* Bb = Ab + 2560;
        #pragma unroll
        for (int k8 = 0; k8 < 2; ++k8) {
            const int kk = k8 * 8;
            uint32_t a[2][4];
            #pragma unroll
            for (int mt = 0; mt < 2; ++mt) {
                int m0 = wm + mt * 16;
                a[mt][0] = __float_as_uint(Ab[(m0 + g)     * 20 + kk + tg]);
                a[mt][1] = __float_as_uint(Ab[(m0 + g + 8) * 20 + kk + tg]);
                a[mt][2] = __float_as_uint(Ab[(m0 + g)     * 20 + kk + tg + 4]);
                a[mt][3] = __float_as_uint(Ab[(m0 + g + 8) * 20 + kk + tg + 4]);
            }
            uint32_t bf[6][2];
            #pragma unroll
            for (int nt = 0; nt < 6; ++nt) {
                int q0 = wn + nt * 8 + g;
                bf[nt][0] = __float_as_uint(Bb[q0 * 20 + kk + tg]);
                bf[nt][1] = __float_as_uint(Bb[q0 * 20 + kk + tg + 4]);
            }
            #pragma unroll
            for (int mt = 0; mt < 2; ++mt) {
                #pragma unroll
                for (int nt = 0; nt < 4; ++nt)
                    MMA_TF32(acc[mt][nt], a[mt], bf[nt]);
                #pragma unroll
                for (int j = 0; j < 2; ++j) {
                    if (ph == 0) { MMA_TF32(accd[0][mt][j], a[mt], bf[4 + j]); }
                    else         { MMA_TF32(accd[1][mt][j], a[mt], bf[4 + j]); }
                }
            }
        }
    };

    // ---- pipeline: 32 stages (16 per phase), 3 smem buffers ----
    issue(0);
    issue(1);
    CPA_WAIT(1);
    __syncthreads();

    int s = 0;
    #pragma unroll 1
    for (; s < 16; ++s) {
        compute(s % 3, 0);
        if (s + 2 < 32) { issue(s + 2); CPA_WAIT(1); }
        else            { CPA_WAIT(0); }
        __syncthreads();
    }
    #pragma unroll 1
    for (; s < 32; ++s) {
        compute(s % 3, 1);
        if (s + 2 < 32) { issue(s + 2); CPA_WAIT(1); }
        else            { CPA_WAIT(0); }
        __syncthreads();
    }

    // ---- epilogue: stage accs into Sacc q-space (pitch 133) ----
    float* Sacc = smf;
    #pragma unroll
    for (int mt = 0; mt < 2; ++mt) {
        int rl = wm + mt * 16 + g;
        #pragma unroll
        for (int nt = 0; nt < 4; ++nt) {
            int npos = wn + nt * 8 + tg * 2;
            int q = (npos < 32) ? npos : npos - 16;
            Sacc[q * 133 + rl]           = acc[mt][nt][0];
            Sacc[(q + 1) * 133 + rl]     = acc[mt][nt][1];
            Sacc[q * 133 + rl + 8]       = acc[mt][nt][2];
            Sacc[(q + 1) * 133 + rl + 8] = acc[mt][nt][3];
        }
        #pragma unroll
        for (int j = 0; j < 2; ++j) {
            int npos = wn + (4 + j) * 8 + tg * 2;
            int qi = (npos < 48) ? npos + 32 : npos;
            int qh = (npos < 48) ? npos + 64 : npos + 32;
            Sacc[qi * 133 + rl]           = accd[0][mt][j][0];
            Sacc[(qi + 1) * 133 + rl]     = accd[0][mt][j][1];
            Sacc[qi * 133 + rl + 8]       = accd[0][mt][j][2];
            Sacc[(qi + 1) * 133 + rl + 8] = accd[0][mt][j][3];
            Sacc[qh * 133 + rl]           = accd[1][mt][j][0];
            Sacc[(qh + 1) * 133 + rl]     = accd[1][mt][j][1];
            Sacc[qh * 133 + rl + 8]       = accd[1][mt][j][2];
            Sacc[(qh + 1) * 133 + rl + 8] = accd[1][mt][j][3];
        }
    }
    __syncthreads();

    // ---- gate math (identical to proven R4 epilogue) ----
    const int col = tid & 31;
    const int c   = c0 + col;
    const int rg0 = (tid >> 5) * 16;
    const float br  = bih[c] + bhh[c];
    const float bz  = bih[256 + c] + bhh[256 + c];
    const float bni = bih[512 + c];
    const float bnh = bhh[512 + c];
    #pragma unroll
    for (int j = 0; j < 16; ++j) {
        int rl = rg0 + j;
        float gr  = Sacc[col * 133 + rl];
        float gz  = Sacc[(32 + col) * 133 + rl];
        float gni = Sacc[(64 + col) * 133 + rl];
        float gnh = Sacc[(96 + col) * 133 + rl];
        float hprev = hin[(r0 + rl) * 256 + c];
        float rg_ = sigf(gr + br);
        float zg_ = sigf(gz + bz);
        float ng_ = tanhf(gni + bni + rg_ * (gnh + bnh));
        hh_out[(r0 + rl) * 256 + c] = (1.f - zg_) * ng_ + zg_ * hprev;
    }
}

// ---------------------------------------------------------------------------
// k3: LayerNorm + fc2 (one warp per row) — unchanged
// ---------------------------------------------------------------------------
__global__ void __launch_bounds__(256) k3_ln_fc2(
    const float* __restrict__ hh, const float* __restrict__ lng,
    const float* __restrict__ lnb, const float* __restrict__ W2,
    const float* __restrict__ b2, float* __restrict__ q, int nrows)
{
    int warp = (blockIdx.x * blockDim.x + threadIdx.x) >> 5;
    int lane = threadIdx.x & 31;
    if (warp >= nrows) return;
    const float* hr = hh + (size_t)warp * RDIM;

    float v[8];
    float s = 0.f;
    #pragma unroll
    for (int i = 0; i < 8; ++i) { v[i] = hr[lane + 32 * i]; s += v[i]; }
    #pragma unroll
    for (int o = 16; o; o >>= 1) s += __shfl_xor_sync(0xffffffffu, s, o);
    float mu = s * (1.f / 256.f);
    float vs = 0.f;
    #pragma unroll
    for (int i = 0; i < 8; ++i) { float d = v[i] - mu; vs += d * d; }
    #pragma unroll
    for (int o = 16; o; o >>= 1) vs += __shfl_xor_sync(0xffffffffu, vs, o);
    float inv = rsqrtf(vs * (1.f / 256.f) + 1e-5f);

    float hn[8];
    #pragma unroll
    for (int i = 0; i < 8; ++i)
        hn[i] = (v[i] - mu) * inv * lng[lane + 32 * i] + lnb[lane + 32 * i];

    #pragma unroll
    for (int j = 0; j < NACT; ++j) {
        float p = 0.f;
        #pragma unroll
        for (int i = 0; i < 8; ++i) p = fmaf(hn[i], W2[j * RDIM + lane + 32 * i], p);
        #pragma unroll
        for (int o = 16; o; o >>= 1) p += __shfl_xor_sync(0xffffffffu, p, o);
        if (lane == j) q[(size_t)warp * NACT + j] = p + b2[j];
    }
}

// ---------------------------------------------------------------------------
extern "C" void kernel_launch(void* const* d_in, const int* in_sizes, int n_in,
                              void* d_out, int out_size)
{
    const float* inputs = (const float*)d_in[0];
    const float* hidden = (const float*)d_in[1];
    const int*   mask   = (const int*)  d_in[2];
    const float* Wfc    = (const float*)d_in[3];
    const float* bfc    = (const float*)d_in[4];
    const float* Wh     = (const float*)d_in[5];
    const float* asrc   = (const float*)d_in[6];
    const float* adst   = (const float*)d_in[7];
    const float* Wo     = (const float*)d_in[8];
    const float* bo     = (const float*)d_in[9];
    const float* W1     = (const float*)d_in[10];
    const float* b1     = (const float*)d_in[11];
    const float* Wih    = (const float*)d_in[12];
    const float* Whh    = (const float*)d_in[13];
    const float* bih    = (const float*)d_in[14];
    const float* bhh    = (const float*)d_in[15];
    const float* lng    = (const float*)d_in[16];
    const float* lnb    = (const float*)d_in[17];
    const float* W2     = (const float*)d_in[18];
    const float* b2     = (const float*)d_in[19];

    const int B = in_sizes[0] / (AN * OBS);       // 4096
    const int nrows = B * AN;                     // 131072
    const int mblk = nrows / 128;                 // 1024

    float* q_out  = (float*)d_out;
    float* hh_out = (float*)d_out + (size_t)nrows * NACT;

    float *xe, *bh, *bg, *wht, *wot;
    cudaGetSymbolAddress((void**)&xe,  g_buf64);
    cudaGetSymbolAddress((void**)&bh,  g_bufH);
    cudaGetSymbolAddress((void**)&bg,  g_bufG);
    cudaGetSymbolAddress((void**)&wht, g_WhT);
    cudaGetSymbolAddress((void**)&wot, g_WoT);

    cudaFuncSetAttribute(kB_attn,   cudaFuncAttributeMaxDynamicSharedMemorySize, KB_SMEM);
    cudaFuncSetAttribute(k2_gru_tc, cudaFuncAttributeMaxDynamicSharedMemorySize, K2_SMEM);

    k0_prep<<<64, 256>>>(Wh, Wo, wht, wot);

    // G1: XE = inputs @ Wfc^T + bfc          [M,64]
    gemm_tn<128, 0, 1><<<dim3(1, mblk), 256, GEMM_SMEM>>>(inputs, nullptr, Wfc, bfc, xe);
    // G2: H = XE @ WhT^T                     [M,256]
    gemm_tn<64, 0, 0><<<dim3(4, mblk), 256, GEMM_SMEM>>>(xe, nullptr, wht, nullptr, bh);
    // attention: agg = softmax(mask, leaky(s_i+s_j)) @ H
    kB_attn<<<B, 128, KB_SMEM>>>(bh, mask, asrc, adst, bg);
    // G3: ATT = agg @ WoT^T + bo             [M,64] (overwrites XE)
    gemm_tn<256, 0, 1><<<dim3(1, mblk), 256, GEMM_SMEM>>>(bg, nullptr, wot, bo, xe);
    // G4: XR = relu([inputs|ATT] @ W1^T+b1)  [M,256] (overwrites agg)
    gemm_tn<128, 64, 2><<<dim3(4, mblk), 256, GEMM_SMEM>>>(inputs, xe, W1, b1, bg);
    // GRU (cp.async tf32 pipeline)
    k2_gru_tc<<<dim3(8, mblk), 256, K2_SMEM>>>(bg, hidden, Wih, Whh, bih, bhh, hh_out);
    // LN + fc2
    k3_ln_fc2<<<(nrows + 7) / 8, 256>>>(hh_out, lng, lnb, W2, b2, q_out, nrows);
}